// round 6
// baseline (speedup 1.0000x reference)
#include <cuda_runtime.h>
#include <cuda_bf16.h>
#include <math.h>
#include <stdint.h>

#define GS    14
#define NQ    196            // GS*GS
#define CDIM  128
#define NH    4
#define HD    32
#define BATCH 1024
#define MTOT  (BATCH * NQ)   // 200704
#define KVN   384            // q(128) | k(128) | v(128)
#define TAB   729            // (2*GS-1)^2
#define SCALE 0.17677669529663688f   // 32^-0.5

// ---- scratch (static device allocations; no cudaMalloc allowed) ----
__device__ float g_pos[TAB * NH];
__device__ __nv_bfloat16 g_qkvh[(size_t)MTOT * KVN];  // qkv hi (q pre-scaled)
__device__ __nv_bfloat16 g_qkvl[(size_t)MTOT * KVN];  // qkv lo
__device__ __nv_bfloat16 g_ath[(size_t)MTOT * CDIM];  // attention out hi
__device__ __nv_bfloat16 g_atl[(size_t)MTOT * CDIM];  // attention out lo
__device__ __nv_bfloat16 g_wqkv_h[KVN * CDIM];        // [n=384][k=128]
__device__ __nv_bfloat16 g_wqkv_l[KVN * CDIM];
__device__ __nv_bfloat16 g_wp_h[CDIM * CDIM];         // [n=128][k=128]
__device__ __nv_bfloat16 g_wp_l[CDIM * CDIM];

// ============================================================
// helpers
// ============================================================
__device__ __forceinline__ uint32_t smem_u32(const void* p) {
    uint32_t a;
    asm("{ .reg .u64 t; cvta.to.shared.u64 t, %1; cvt.u32.u64 %0, t; }"
        : "=r"(a) : "l"(p));
    return a;
}
__device__ __forceinline__ void ldsm_x4(uint32_t& r0, uint32_t& r1,
                                        uint32_t& r2, uint32_t& r3, uint32_t addr) {
    asm volatile("ldmatrix.sync.aligned.m8n8.x4.shared.b16 {%0,%1,%2,%3}, [%4];"
                 : "=r"(r0), "=r"(r1), "=r"(r2), "=r"(r3) : "r"(addr));
}
__device__ __forceinline__ void ldsm_x4t(uint32_t& r0, uint32_t& r1,
                                         uint32_t& r2, uint32_t& r3, uint32_t addr) {
    asm volatile("ldmatrix.sync.aligned.m8n8.x4.trans.shared.b16 {%0,%1,%2,%3}, [%4];"
                 : "=r"(r0), "=r"(r1), "=r"(r2), "=r"(r3) : "r"(addr));
}
__device__ __forceinline__ void mma16816(float* d, const uint32_t* a, const uint32_t* b) {
    asm volatile("mma.sync.aligned.m16n8k16.row.col.f32.bf16.bf16.f32 "
                 "{%0,%1,%2,%3}, {%4,%5,%6,%7}, {%8,%9}, {%0,%1,%2,%3};"
                 : "+f"(d[0]), "+f"(d[1]), "+f"(d[2]), "+f"(d[3])
                 : "r"(a[0]), "r"(a[1]), "r"(a[2]), "r"(a[3]),
                   "r"(b[0]), "r"(b[1]));
}
__device__ __forceinline__ void split2(float v0, float v1, uint32_t& hi, uint32_t& lo) {
    __nv_bfloat16 h0 = __float2bfloat16(v0), h1 = __float2bfloat16(v1);
    __nv_bfloat162 H = __halves2bfloat162(h0, h1);
    __nv_bfloat162 L = __halves2bfloat162(
        __float2bfloat16(v0 - __bfloat162float(h0)),
        __float2bfloat16(v1 - __bfloat162float(h1)));
    hi = *(uint32_t*)&H;
    lo = *(uint32_t*)&L;
}
// swizzled byte offset inside a 128x128 bf16 tile (256B rows, 16B chunks)
__device__ __forceinline__ uint32_t swz(int row, int chunk) {
    return (uint32_t)(row * 256 + ((chunk ^ (row & 7)) << 4));
}

// ============================================================
// Kernel 1: dynamic position-bias MLP (729 rows, tiny)
// ============================================================
__device__ __forceinline__ void ln_relu8(float* x, const float* g, const float* b) {
    float mu = 0.f;
#pragma unroll
    for (int d = 0; d < 8; d++) mu += x[d];
    mu *= 0.125f;
    float var = 0.f;
#pragma unroll
    for (int d = 0; d < 8; d++) { float t = x[d] - mu; var += t * t; }
    var *= 0.125f;
    float inv = rsqrtf(var + 1e-5f);
#pragma unroll
    for (int d = 0; d < 8; d++) {
        float t = (x[d] - mu) * inv * g[d] + b[d];
        x[d] = t > 0.f ? t : 0.f;
    }
}

__global__ void pos_mlp_kernel(
    const float* __restrict__ pp_w, const float* __restrict__ pp_b,
    const float* __restrict__ ln1_g, const float* __restrict__ ln1_b,
    const float* __restrict__ l1_w,  const float* __restrict__ l1_b,
    const float* __restrict__ ln2_g, const float* __restrict__ ln2_b,
    const float* __restrict__ l2_w,  const float* __restrict__ l2_b,
    const float* __restrict__ ln3_g, const float* __restrict__ ln3_b,
    const float* __restrict__ l3_w,  const float* __restrict__ l3_b)
{
    int m = blockIdx.x * blockDim.x + threadIdx.x;
    if (m >= TAB) return;
    float bi = (float)(m / 27 - 13);
    float bj = (float)(m % 27 - 13);
    float h[8], t[8];
#pragma unroll
    for (int d = 0; d < 8; d++) h[d] = bi * pp_w[d] + bj * pp_w[8 + d] + pp_b[d];
    ln_relu8(h, ln1_g, ln1_b);
#pragma unroll
    for (int j = 0; j < 8; j++) {
        float a = l1_b[j];
#pragma unroll
        for (int d = 0; d < 8; d++) a += h[d] * l1_w[d * 8 + j];
        t[j] = a;
    }
    ln_relu8(t, ln2_g, ln2_b);
#pragma unroll
    for (int j = 0; j < 8; j++) {
        float a = l2_b[j];
#pragma unroll
        for (int d = 0; d < 8; d++) a += t[d] * l2_w[d * 8 + j];
        h[j] = a;
    }
    ln_relu8(h, ln3_g, ln3_b);
#pragma unroll
    for (int j = 0; j < NH; j++) {
        float a = l3_b[j];
#pragma unroll
        for (int d = 0; d < 8; d++) a += h[d] * l3_w[d * NH + j];
        g_pos[m * NH + j] = a;
    }
}

// ============================================================
// Kernel: weight prep — transpose to [n][k], bf16 hi/lo split
// ============================================================
__global__ __launch_bounds__(256) void wprep_kernel(
    const float* __restrict__ wq, const float* __restrict__ wkv,
    const float* __restrict__ wproj)
{
    int idx = blockIdx.x * 256 + threadIdx.x;
    if (idx < KVN * CDIM) {
        int n = idx >> 7, k = idx & 127;
        float v = (n < 128) ? wq[k * 128 + n] : wkv[k * 256 + (n - 128)];
        __nv_bfloat16 h = __float2bfloat16(v);
        g_wqkv_h[idx] = h;
        g_wqkv_l[idx] = __float2bfloat16(v - __bfloat162float(h));
    } else if (idx < KVN * CDIM + CDIM * CDIM) {
        int j = idx - KVN * CDIM;
        int n = j >> 7, k = j & 127;
        float v = wproj[k * 128 + n];
        __nv_bfloat16 h = __float2bfloat16(v);
        g_wp_h[j] = h;
        g_wp_l[j] = __float2bfloat16(v - __bfloat162float(h));
    }
}

// ============================================================
// Kernel: HMMA GEMM, 3-term split
//   mode 0: A = x (fp32, fused split), out = g_qkvh/g_qkvl bf16 (q scaled)
//   mode 1: A = g_ath/g_atl (pre-split), out = fp32 + bias
// ============================================================
#define TILEB 32768
#define SM_AH 0
#define SM_AL TILEB
#define SM_BH (2 * TILEB)
#define SM_BL (3 * TILEB)
#define GSMEM (4 * TILEB)

__global__ __launch_bounds__(256) void hmma_gemm_kernel(
    int mode, const float* __restrict__ Ain,
    float* __restrict__ Cout, const float* __restrict__ bias)
{
    extern __shared__ char smc[];
    const uint32_t sb = smem_u32(smc);
    const int tid = threadIdx.x;
    const int w = tid >> 5, lane = tid & 31;
    const int m0 = blockIdx.x * 128;

    const __nv_bfloat16* Bh = (mode == 0) ? g_wqkv_h : g_wp_h;
    const __nv_bfloat16* Bl = (mode == 0) ? g_wqkv_l : g_wp_l;
    const int NB = (mode == 0) ? 3 : 1;

    // ---- stage A ----
    if (mode == 0) {
        for (int idx = tid; idx < 2048; idx += 256) {
            int row = idx >> 4, c = idx & 15;
            const float* src = Ain + (size_t)(m0 + row) * CDIM + c * 8;
            float4 v0 = *(const float4*)src;
            float4 v1 = *(const float4*)(src + 4);
            float f[8] = {v0.x, v0.y, v0.z, v0.w, v1.x, v1.y, v1.z, v1.w};
            uint32_t hp[4], lp[4];
#pragma unroll
            for (int q = 0; q < 4; q++)
                split2(f[2 * q], f[2 * q + 1], hp[q], lp[q]);
            uint32_t off = swz(row, c);
            *(uint4*)(smc + SM_AH + off) = make_uint4(hp[0], hp[1], hp[2], hp[3]);
            *(uint4*)(smc + SM_AL + off) = make_uint4(lp[0], lp[1], lp[2], lp[3]);
        }
    } else {
        for (int idx = tid; idx < 2048; idx += 256) {
            int row = idx >> 4, c = idx & 15;
            size_t gi = (size_t)(m0 + row) * CDIM + c * 8;
            uint32_t off = swz(row, c);
            *(uint4*)(smc + SM_AH + off) = *(const uint4*)(g_ath + gi);
            *(uint4*)(smc + SM_AL + off) = *(const uint4*)(g_atl + gi);
        }
    }

    const int wm = w >> 1;
    const int wn = w & 1;
    const int lrow = lane & 15;
    const int lchunk = lane >> 4;

    for (int nb = 0; nb < NB; nb++) {
        const int n0 = nb * 128;
        __syncthreads();

        for (int idx = tid; idx < 2048; idx += 256) {
            int row = idx >> 4, c = idx & 15;
            size_t gi = (size_t)(n0 + row) * CDIM + c * 8;
            uint32_t off = swz(row, c);
            *(uint4*)(smc + SM_BH + off) = *(const uint4*)(Bh + gi);
            *(uint4*)(smc + SM_BL + off) = *(const uint4*)(Bl + gi);
        }
        __syncthreads();

        float d[2][8][4];
#pragma unroll
        for (int mi = 0; mi < 2; mi++)
#pragma unroll
            for (int ni = 0; ni < 8; ni++)
#pragma unroll
                for (int q = 0; q < 4; q++) d[mi][ni][q] = 0.f;

#pragma unroll
        for (int ks = 0; ks < 8; ks++) {
            const int chunk = ks * 2 + lchunk;
            uint32_t ah[2][4], al[2][4];
#pragma unroll
            for (int mi = 0; mi < 2; mi++) {
                int row = wm * 32 + mi * 16 + lrow;
                ldsm_x4(ah[mi][0], ah[mi][1], ah[mi][2], ah[mi][3],
                        sb + SM_AH + swz(row, chunk));
                ldsm_x4(al[mi][0], al[mi][1], al[mi][2], al[mi][3],
                        sb + SM_AL + swz(row, chunk));
            }
#pragma unroll
            for (int np = 0; np < 4; np++) {
                int row = wn * 64 + np * 16 + lrow;
                uint32_t r0, r1, r2, r3;
                // Bh: used by Ah and Al
                ldsm_x4(r0, r1, r2, r3, sb + SM_BH + swz(row, chunk));
                {
                    uint32_t b0[2] = {r0, r2}, b1[2] = {r1, r3};
#pragma unroll
                    for (int mi = 0; mi < 2; mi++) {
                        mma16816(d[mi][2 * np], ah[mi], b0);
                        mma16816(d[mi][2 * np + 1], ah[mi], b1);
                        mma16816(d[mi][2 * np], al[mi], b0);
                        mma16816(d[mi][2 * np + 1], al[mi], b1);
                    }
                }
                // Bl: used by Ah
                ldsm_x4(r0, r1, r2, r3, sb + SM_BL + swz(row, chunk));
                {
                    uint32_t b0[2] = {r0, r2}, b1[2] = {r1, r3};
#pragma unroll
                    for (int mi = 0; mi < 2; mi++) {
                        mma16816(d[mi][2 * np], ah[mi], b0);
                        mma16816(d[mi][2 * np + 1], ah[mi], b1);
                    }
                }
            }
        }

        // ---- epilogue ----
        const int mrow = m0 + wm * 32 + (lane >> 2);
        const int ncol = n0 + wn * 64 + (lane & 3) * 2;
        if (mode == 0) {
            const float sc = (nb == 0) ? SCALE : 1.f;
#pragma unroll
            for (int mi = 0; mi < 2; mi++) {
#pragma unroll
                for (int ni = 0; ni < 8; ni++) {
                    uint32_t hi, lo;
                    size_t p0 = (size_t)(mrow + mi * 16) * KVN + ncol + ni * 8;
                    size_t p1 = (size_t)(mrow + mi * 16 + 8) * KVN + ncol + ni * 8;
                    split2(d[mi][ni][0] * sc, d[mi][ni][1] * sc, hi, lo);
                    *(uint32_t*)(g_qkvh + p0) = hi;
                    *(uint32_t*)(g_qkvl + p0) = lo;
                    split2(d[mi][ni][2] * sc, d[mi][ni][3] * sc, hi, lo);
                    *(uint32_t*)(g_qkvh + p1) = hi;
                    *(uint32_t*)(g_qkvl + p1) = lo;
                }
            }
        } else {
#pragma unroll
            for (int mi = 0; mi < 2; mi++) {
#pragma unroll
                for (int ni = 0; ni < 8; ni++) {
                    float b0 = bias[ncol + ni * 8];
                    float b1 = bias[ncol + ni * 8 + 1];
                    float* p0 = Cout + (size_t)(mrow + mi * 16) * CDIM + ncol + ni * 8;
                    float* p1 = Cout + (size_t)(mrow + mi * 16 + 8) * CDIM + ncol + ni * 8;
                    *(float2*)p0 = make_float2(d[mi][ni][0] + b0, d[mi][ni][1] + b1);
                    *(float2*)p1 = make_float2(d[mi][ni][2] + b0, d[mi][ni][3] + b1);
                }
            }
        }
    }
}

// ============================================================
// HMMA flash attention: one CTA per (b,h), 8 warps
//   Q/K/V hi/lo: [208 rows][32 d] bf16, row stride 80 B
//   PV B-frags via ldmatrix.trans on V rows (no transpose buffer)
// ============================================================
#define AQH 0
#define AQL 16640
#define AKH 33280
#define AKL 49920
#define AVH 66560
#define AVL 83200
#define ASPOSH 99840                      // per-head bias table, 729 floats
#define ACOLC (ASPOSH + TAB * 4)          // 102756
#define ATTN_SMEM (ACOLC + 208 * 4)       // 103588

template<int NSTART, int NT>
__device__ __forceinline__ void half_pass(
    uint32_t sb, const float* __restrict__ sposh, const int* __restrict__ colC,
    int m0, int R0, int R1, int lane,
    float o[4][4], float& mo0, float& mo1, float& sum0, float& sum1)
{
    const int lrow = lane & 15, lhalf = lane >> 4;
    float S[NT][4];
#pragma unroll
    for (int j = 0; j < NT; j++)
#pragma unroll
        for (int q = 0; q < 4; q++) S[j][q] = 0.f;

    // ---- QK^T: S = QhKh + QlKh + QhKl ----
#pragma unroll
    for (int k0 = 0; k0 < 2; k0++) {
        uint32_t aoff = (uint32_t)((m0 + lrow) * 80 + (k0 * 2 + lhalf) * 16);
        uint32_t ah[4], al[4];
        ldsm_x4(ah[0], ah[1], ah[2], ah[3], sb + AQH + aoff);
        ldsm_x4(al[0], al[1], al[2], al[3], sb + AQL + aoff);
#pragma unroll
        for (int np = 0; np < NT / 2; np++) {
            uint32_t boff = (uint32_t)(((NSTART + 2 * np) * 8 + lrow) * 80
                                       + (k0 * 2 + lhalf) * 16);
            uint32_t r0, r1, r2, r3;
            ldsm_x4(r0, r1, r2, r3, sb + AKH + boff);
            {
                uint32_t b0[2] = {r0, r2}, b1[2] = {r1, r3};
                mma16816(S[2 * np], ah, b0);
                mma16816(S[2 * np + 1], ah, b1);
                mma16816(S[2 * np], al, b0);
                mma16816(S[2 * np + 1], al, b1);
            }
            ldsm_x4(r0, r1, r2, r3, sb + AKL + boff);
            {
                uint32_t b0[2] = {r0, r2}, b1[2] = {r1, r3};
                mma16816(S[2 * np], ah, b0);
                mma16816(S[2 * np + 1], ah, b1);
            }
        }
    }

    // ---- bias + mask + row max ----
    float ml0 = -1e30f, ml1 = -1e30f;
#pragma unroll
    for (int j = 0; j < NT; j++) {
        int c0 = (NSTART + j) * 8 + (lane & 3) * 2;
#pragma unroll
        for (int e = 0; e < 2; e++) {
            int c = c0 + e;
            if (c < NQ) {
                int C4 = colC[c];
                S[j][e]     += sposh[R0 - C4];
                S[j][2 + e] += sposh[R1 - C4];
            } else {
                S[j][e] = -1e30f;
                S[j][2 + e] = -1e30f;
            }
        }
        ml0 = fmaxf(ml0, fmaxf(S[j][0], S[j][1]));
        ml1 = fmaxf(ml1, fmaxf(S[j][2], S[j][3]));
    }
    ml0 = fmaxf(ml0, __shfl_xor_sync(0xffffffffu, ml0, 1));
    ml0 = fmaxf(ml0, __shfl_xor_sync(0xffffffffu, ml0, 2));
    ml1 = fmaxf(ml1, __shfl_xor_sync(0xffffffffu, ml1, 1));
    ml1 = fmaxf(ml1, __shfl_xor_sync(0xffffffffu, ml1, 2));
    float mn0 = fmaxf(mo0, ml0), mn1 = fmaxf(mo1, ml1);
    float f0 = __expf(mo0 - mn0), f1 = __expf(mo1 - mn1);
    mo0 = mn0; mo1 = mn1;
    sum0 *= f0; sum1 *= f1;
#pragma unroll
    for (int n = 0; n < 4; n++) {
        o[n][0] *= f0; o[n][1] *= f0;
        o[n][2] *= f1; o[n][3] *= f1;
    }

    // ---- P = exp(S-m) hi/lo; PV with trans-ldmatrix V frags ----
#pragma unroll
    for (int t = 0; t < NT / 2; t++) {
        uint32_t ah[4], al[4];
#pragma unroll
        for (int jj = 0; jj < 2; jj++) {
            int j = 2 * t + jj;
            float p0 = __expf(S[j][0] - mn0);
            float p1 = __expf(S[j][1] - mn0);
            float p2 = __expf(S[j][2] - mn1);
            float p3 = __expf(S[j][3] - mn1);
            sum0 += p0 + p1; sum1 += p2 + p3;
            split2(p0, p1, ah[2 * jj], al[2 * jj]);
            split2(p2, p3, ah[2 * jj + 1], al[2 * jj + 1]);
        }
        const int kk0 = NSTART * 8 + t * 16;
#pragma unroll
        for (int dh = 0; dh < 2; dh++) {       // d halves: 0..15, 16..31
            uint32_t voff = (uint32_t)((kk0 + lrow) * 80
                                       + (dh * 16 + lhalf * 8) * 2);
            uint32_t r0, r1, r2, r3;
            ldsm_x4t(r0, r1, r2, r3, sb + AVH + voff);
            {
                uint32_t b0[2] = {r0, r1}, b1[2] = {r2, r3};
                mma16816(o[2 * dh], ah, b0);
                mma16816(o[2 * dh + 1], ah, b1);
                mma16816(o[2 * dh], al, b0);
                mma16816(o[2 * dh + 1], al, b1);
            }
            ldsm_x4t(r0, r1, r2, r3, sb + AVL + voff);
            {
                uint32_t b0[2] = {r0, r1}, b1[2] = {r2, r3};
                mma16816(o[2 * dh], ah, b0);
                mma16816(o[2 * dh + 1], ah, b1);
            }
        }
    }
}

__global__ __launch_bounds__(256, 2) void fattn_kernel()
{
    extern __shared__ char smb[];
    const uint32_t sb = smem_u32(smb);
    float* sposh = (float*)(smb + ASPOSH);
    int* colC = (int*)(smb + ACOLC);
    const int b = blockIdx.x, h = blockIdx.y;
    const int tid = threadIdx.x;

    // ---- stage q/k/v hi+lo rows (pure 16B copies; rows>=NQ zeroed) ----
    const __nv_bfloat16* srcH = g_qkvh + (size_t)b * NQ * KVN + h * HD;
    const __nv_bfloat16* srcL = g_qkvl + (size_t)b * NQ * KVN + h * HD;
    for (int idx = tid; idx < 4992; idx += 256) {
        int row = idx / 24, rem = idx % 24;
        int sec = rem >> 3, hl = (rem >> 2) & 1, u4 = rem & 3;
        uint4 v = make_uint4(0u, 0u, 0u, 0u);
        if (row < NQ) {
            const __nv_bfloat16* s = (hl ? srcL : srcH)
                + (size_t)row * KVN + sec * 128 + u4 * 8;
            v = *(const uint4*)s;
        }
        *(uint4*)(smb + sec * 33280 + hl * 16640 + row * 80 + u4 * 16) = v;
    }
    for (int i = tid; i < TAB; i += 256) sposh[i] = g_pos[i * NH + h];
    for (int c = tid; c < 208; c += 256) colC[c] = (c / 14) * 27 + c % 14;
    __syncthreads();

    const int w = tid >> 5, lane = tid & 31;
    for (int s = w; s < 13; s += 8) {
        const int m0 = s * 16;
        const int row0 = m0 + (lane >> 2), row1 = row0 + 8;
        const int rc0 = min(row0, NQ - 1), rc1 = min(row1, NQ - 1);
        const int R0 = (rc0 / 14) * 27 + rc0 % 14 + 364;
        const int R1 = (rc1 / 14) * 27 + rc1 % 14 + 364;

        float o[4][4];
#pragma unroll
        for (int n = 0; n < 4; n++)
#pragma unroll
            for (int q = 0; q < 4; q++) o[n][q] = 0.f;
        float mo0 = -1e30f, mo1 = -1e30f, sum0 = 0.f, sum1 = 0.f;

        half_pass<0, 14>(sb, sposh, colC, m0, R0, R1, lane,
                         o, mo0, mo1, sum0, sum1);
        half_pass<14, 12>(sb, sposh, colC, m0, R0, R1, lane,
                          o, mo0, mo1, sum0, sum1);

        sum0 += __shfl_xor_sync(0xffffffffu, sum0, 1);
        sum0 += __shfl_xor_sync(0xffffffffu, sum0, 2);
        sum1 += __shfl_xor_sync(0xffffffffu, sum1, 1);
        sum1 += __shfl_xor_sync(0xffffffffu, sum1, 2);
        float i0 = 1.f / sum0, i1 = 1.f / sum1;

#pragma unroll
        for (int n = 0; n < 4; n++) {
            int d0 = n * 8 + (lane & 3) * 2;
            uint32_t hi, lo;
            if (row0 < NQ) {
                size_t p = ((size_t)b * NQ + row0) * CDIM + h * HD + d0;
                split2(o[n][0] * i0, o[n][1] * i0, hi, lo);
                *(uint32_t*)(g_ath + p) = hi;
                *(uint32_t*)(g_atl + p) = lo;
            }
            if (row1 < NQ) {
                size_t p = ((size_t)b * NQ + row1) * CDIM + h * HD + d0;
                split2(o[n][2] * i1, o[n][3] * i1, hi, lo);
                *(uint32_t*)(g_ath + p) = hi;
                *(uint32_t*)(g_atl + p) = lo;
            }
        }
    }
}

// ============================================================
// launch
// ============================================================
extern "C" void kernel_launch(void* const* d_in, const int* in_sizes, int n_in,
                              void* d_out, int out_size)
{
    const float* x     = (const float*)d_in[0];
    const float* wq    = (const float*)d_in[1];
    const float* wkv   = (const float*)d_in[2];
    const float* wproj = (const float*)d_in[3];
    const float* bproj = (const float*)d_in[4];
    const float* pp_w  = (const float*)d_in[5];
    const float* pp_b  = (const float*)d_in[6];
    const float* ln1_g = (const float*)d_in[7];
    const float* ln1_b = (const float*)d_in[8];
    const float* l1_w  = (const float*)d_in[9];
    const float* l1_b  = (const float*)d_in[10];
    const float* ln2_g = (const float*)d_in[11];
    const float* ln2_b = (const float*)d_in[12];
    const float* l2_w  = (const float*)d_in[13];
    const float* l2_b  = (const float*)d_in[14];
    const float* ln3_g = (const float*)d_in[15];
    const float* ln3_b = (const float*)d_in[16];
    const float* l3_w  = (const float*)d_in[17];
    const float* l3_b  = (const float*)d_in[18];
    float* out = (float*)d_out;

    cudaFuncSetAttribute(hmma_gemm_kernel,
                         cudaFuncAttributeMaxDynamicSharedMemorySize, GSMEM);
    cudaFuncSetAttribute(fattn_kernel,
                         cudaFuncAttributeMaxDynamicSharedMemorySize, ATTN_SMEM);

    pos_mlp_kernel<<<3, 256>>>(pp_w, pp_b, ln1_g, ln1_b, l1_w, l1_b,
                               ln2_g, ln2_b, l2_w, l2_b,
                               ln3_g, ln3_b, l3_w, l3_b);

    wprep_kernel<<<256, 256>>>(wq, wkv, wproj);

    // QKV: x @ [wq|wkv] -> g_qkvh/g_qkvl (bf16, q pre-scaled)
    hmma_gemm_kernel<<<MTOT / 128, 256, GSMEM>>>(0, x, nullptr, nullptr);

    // flash attention -> g_ath/g_atl (bf16 split)
    fattn_kernel<<<dim3(BATCH, NH), 256, ATTN_SMEM>>>();

    // Proj: att @ wproj + bproj -> out (fp32)
    hmma_gemm_kernel<<<MTOT / 128, 256, GSMEM>>>(1, nullptr, out, bproj);
}

// round 7
// speedup vs baseline: 1.2400x; 1.2400x over previous
#include <cuda_runtime.h>
#include <cuda_bf16.h>
#include <math.h>
#include <stdint.h>

#define GS    14
#define NQ    196            // GS*GS
#define CDIM  128
#define NH    4
#define HD    32
#define BATCH 1024
#define MTOT  (BATCH * NQ)   // 200704
#define KVN   384            // q(128) | k(128) | v(128)
#define TAB   729            // (2*GS-1)^2
#define SCALE 0.17677669529663688f   // 32^-0.5

// ---- scratch (static device allocations; no cudaMalloc allowed) ----
__device__ float g_qkv[(size_t)MTOT * KVN];   // ~308 MB
__device__ float g_att[(size_t)MTOT * CDIM];  // ~103 MB
__device__ float g_pos[TAB * NH];
__device__ __nv_bfloat16 g_wqkv_h[KVN * CDIM];   // [n=384][k=128]
__device__ __nv_bfloat16 g_wqkv_l[KVN * CDIM];
__device__ __nv_bfloat16 g_wp_h[CDIM * CDIM];    // [n=128][k=128]
__device__ __nv_bfloat16 g_wp_l[CDIM * CDIM];

// ============================================================
// helpers
// ============================================================
__device__ __forceinline__ uint32_t smem_u32(const void* p) {
    uint32_t a;
    asm("{ .reg .u64 t; cvta.to.shared.u64 t, %1; cvt.u32.u64 %0, t; }"
        : "=r"(a) : "l"(p));
    return a;
}
__device__ __forceinline__ void ldsm_x4(uint32_t& r0, uint32_t& r1,
                                        uint32_t& r2, uint32_t& r3, uint32_t addr) {
    asm volatile("ldmatrix.sync.aligned.m8n8.x4.shared.b16 {%0,%1,%2,%3}, [%4];"
                 : "=r"(r0), "=r"(r1), "=r"(r2), "=r"(r3) : "r"(addr));
}
__device__ __forceinline__ void ldsm_x4t(uint32_t& r0, uint32_t& r1,
                                         uint32_t& r2, uint32_t& r3, uint32_t addr) {
    asm volatile("ldmatrix.sync.aligned.m8n8.x4.trans.shared.b16 {%0,%1,%2,%3}, [%4];"
                 : "=r"(r0), "=r"(r1), "=r"(r2), "=r"(r3) : "r"(addr));
}
__device__ __forceinline__ void mma16816(float* d, const uint32_t* a, const uint32_t* b) {
    asm volatile("mma.sync.aligned.m16n8k16.row.col.f32.bf16.bf16.f32 "
                 "{%0,%1,%2,%3}, {%4,%5,%6,%7}, {%8,%9}, {%0,%1,%2,%3};"
                 : "+f"(d[0]), "+f"(d[1]), "+f"(d[2]), "+f"(d[3])
                 : "r"(a[0]), "r"(a[1]), "r"(a[2]), "r"(a[3]),
                   "r"(b[0]), "r"(b[1]));
}
__device__ __forceinline__ void split2(float v0, float v1, uint32_t& hi, uint32_t& lo) {
    __nv_bfloat16 h0 = __float2bfloat16(v0), h1 = __float2bfloat16(v1);
    __nv_bfloat162 H = __halves2bfloat162(h0, h1);
    __nv_bfloat162 L = __halves2bfloat162(
        __float2bfloat16(v0 - __bfloat162float(h0)),
        __float2bfloat16(v1 - __bfloat162float(h1)));
    hi = *(uint32_t*)&H;
    lo = *(uint32_t*)&L;
}
// swizzled byte offset inside a [rows]x128 bf16 tile (256B rows, 16B chunks)
__device__ __forceinline__ uint32_t swz(int row, int chunk) {
    return (uint32_t)(row * 256 + ((chunk ^ (row & 7)) << 4));
}

// ============================================================
// Kernel 1: dynamic position-bias MLP (729 rows, tiny)
// ============================================================
__device__ __forceinline__ void ln_relu8(float* x, const float* g, const float* b) {
    float mu = 0.f;
#pragma unroll
    for (int d = 0; d < 8; d++) mu += x[d];
    mu *= 0.125f;
    float var = 0.f;
#pragma unroll
    for (int d = 0; d < 8; d++) { float t = x[d] - mu; var += t * t; }
    var *= 0.125f;
    float inv = rsqrtf(var + 1e-5f);
#pragma unroll
    for (int d = 0; d < 8; d++) {
        float t = (x[d] - mu) * inv * g[d] + b[d];
        x[d] = t > 0.f ? t : 0.f;
    }
}

__global__ void pos_mlp_kernel(
    const float* __restrict__ pp_w, const float* __restrict__ pp_b,
    const float* __restrict__ ln1_g, const float* __restrict__ ln1_b,
    const float* __restrict__ l1_w,  const float* __restrict__ l1_b,
    const float* __restrict__ ln2_g, const float* __restrict__ ln2_b,
    const float* __restrict__ l2_w,  const float* __restrict__ l2_b,
    const float* __restrict__ ln3_g, const float* __restrict__ ln3_b,
    const float* __restrict__ l3_w,  const float* __restrict__ l3_b)
{
    int m = blockIdx.x * blockDim.x + threadIdx.x;
    if (m >= TAB) return;
    float bi = (float)(m / 27 - 13);
    float bj = (float)(m % 27 - 13);
    float h[8], t[8];
#pragma unroll
    for (int d = 0; d < 8; d++) h[d] = bi * pp_w[d] + bj * pp_w[8 + d] + pp_b[d];
    ln_relu8(h, ln1_g, ln1_b);
#pragma unroll
    for (int j = 0; j < 8; j++) {
        float a = l1_b[j];
#pragma unroll
        for (int d = 0; d < 8; d++) a += h[d] * l1_w[d * 8 + j];
        t[j] = a;
    }
    ln_relu8(t, ln2_g, ln2_b);
#pragma unroll
    for (int j = 0; j < 8; j++) {
        float a = l2_b[j];
#pragma unroll
        for (int d = 0; d < 8; d++) a += t[d] * l2_w[d * 8 + j];
        h[j] = a;
    }
    ln_relu8(h, ln3_g, ln3_b);
#pragma unroll
    for (int j = 0; j < NH; j++) {
        float a = l3_b[j];
#pragma unroll
        for (int d = 0; d < 8; d++) a += h[d] * l3_w[d * NH + j];
        g_pos[m * NH + j] = a;
    }
}

// ============================================================
// Kernel: weight prep — transpose to [n][k], bf16 hi/lo split
// ============================================================
__global__ __launch_bounds__(256) void wprep_kernel(
    const float* __restrict__ wq, const float* __restrict__ wkv,
    const float* __restrict__ wproj)
{
    int idx = blockIdx.x * 256 + threadIdx.x;
    if (idx < KVN * CDIM) {
        int n = idx >> 7, k = idx & 127;
        float v = (n < 128) ? wq[k * 128 + n] : wkv[k * 256 + (n - 128)];
        __nv_bfloat16 h = __float2bfloat16(v);
        g_wqkv_h[idx] = h;
        g_wqkv_l[idx] = __float2bfloat16(v - __bfloat162float(h));
    } else if (idx < KVN * CDIM + CDIM * CDIM) {
        int j = idx - KVN * CDIM;
        int n = j >> 7, k = j & 127;
        float v = wproj[k * 128 + n];
        __nv_bfloat16 h = __float2bfloat16(v);
        g_wp_h[j] = h;
        g_wp_l[j] = __float2bfloat16(v - __bfloat162float(h));
    }
}

// ============================================================
// Kernel: HMMA GEMM, 3-term split, B chunked in 64-row pieces
//   smem 96KB -> 2 CTAs/SM (vs 128KB -> 1 CTA/SM in R5)
//   mode 0: A = x (fp32, fused split), C = g_qkv (fp32, no bias), 6 chunks
//   mode 1: A = g_att (fp32, fused split), C = out + bias, 2 chunks
// ============================================================
#define SM_AH 0
#define SM_AL 32768
#define SM_BH 65536
#define SM_BL 81920
#define GSMEM 98304

__global__ __launch_bounds__(256, 2) void hmma_gemm_kernel(
    int mode, const float* __restrict__ Ain,
    float* __restrict__ Cout, const float* __restrict__ bias)
{
    extern __shared__ char smc[];
    const uint32_t sb = smem_u32(smc);
    const int tid = threadIdx.x;
    const int w = tid >> 5, lane = tid & 31;
    const int m0 = blockIdx.x * 128;

    const float* A = (mode == 0) ? Ain : g_att;
    float* C = (mode == 0) ? g_qkv : Cout;
    const __nv_bfloat16* Bh = (mode == 0) ? g_wqkv_h : g_wp_h;
    const __nv_bfloat16* Bl = (mode == 0) ? g_wqkv_l : g_wp_l;
    const int NCH = (mode == 0) ? 6 : 2;       // 64-row B chunks
    const int ldc = (mode == 0) ? KVN : CDIM;
    const bool has_bias = (mode == 1);

    // ---- stage A: fp32 -> bf16 hi/lo, swizzled smem (128 rows) ----
    for (int idx = tid; idx < 2048; idx += 256) {
        int row = idx >> 4, c = idx & 15;
        const float* src = A + (size_t)(m0 + row) * CDIM + c * 8;
        float4 v0 = *(const float4*)src;
        float4 v1 = *(const float4*)(src + 4);
        float f[8] = {v0.x, v0.y, v0.z, v0.w, v1.x, v1.y, v1.z, v1.w};
        uint32_t hp[4], lp[4];
#pragma unroll
        for (int q = 0; q < 4; q++)
            split2(f[2 * q], f[2 * q + 1], hp[q], lp[q]);
        uint32_t off = swz(row, c);
        *(uint4*)(smc + SM_AH + off) = make_uint4(hp[0], hp[1], hp[2], hp[3]);
        *(uint4*)(smc + SM_AL + off) = make_uint4(lp[0], lp[1], lp[2], lp[3]);
    }

    const int wm = w >> 1;        // 0..3 -> 32 m-rows
    const int wn = w & 1;         // 0..1 -> 32 n-cols of the 64-col chunk
    const int lrow = lane & 15;
    const int lchunk = lane >> 4;

    for (int ch = 0; ch < NCH; ch++) {
        const int n0 = ch * 64;
        __syncthreads();   // prior chunk's B reads done (covers A stage on ch=0)

        // ---- stage B chunk: 64 rows hi+lo ----
        for (int idx = tid; idx < 1024; idx += 256) {
            int row = idx >> 4, c = idx & 15;
            size_t gi = (size_t)(n0 + row) * CDIM + c * 8;
            uint32_t off = swz(row, c);
            *(uint4*)(smc + SM_BH + off) = *(const uint4*)(Bh + gi);
            *(uint4*)(smc + SM_BL + off) = *(const uint4*)(Bl + gi);
        }
        __syncthreads();

        float d[2][4][4];
#pragma unroll
        for (int mi = 0; mi < 2; mi++)
#pragma unroll
            for (int ni = 0; ni < 4; ni++)
#pragma unroll
                for (int q = 0; q < 4; q++) d[mi][ni][q] = 0.f;

#pragma unroll
        for (int ks = 0; ks < 8; ks++) {
            const int chunk = ks * 2 + lchunk;
            uint32_t ah[2][4], al[2][4];
#pragma unroll
            for (int mi = 0; mi < 2; mi++) {
                int row = wm * 32 + mi * 16 + lrow;
                ldsm_x4(ah[mi][0], ah[mi][1], ah[mi][2], ah[mi][3],
                        sb + SM_AH + swz(row, chunk));
                ldsm_x4(al[mi][0], al[mi][1], al[mi][2], al[mi][3],
                        sb + SM_AL + swz(row, chunk));
            }
#pragma unroll
            for (int np = 0; np < 2; np++) {
                int row = wn * 32 + np * 16 + lrow;
                uint32_t r0, r1, r2, r3;
                // Bh: consumed by Ah and Al
                ldsm_x4(r0, r1, r2, r3, sb + SM_BH + swz(row, chunk));
                {
                    uint32_t b0[2] = {r0, r2}, b1[2] = {r1, r3};
#pragma unroll
                    for (int mi = 0; mi < 2; mi++) {
                        mma16816(d[mi][2 * np], ah[mi], b0);
                        mma16816(d[mi][2 * np + 1], ah[mi], b1);
                        mma16816(d[mi][2 * np], al[mi], b0);
                        mma16816(d[mi][2 * np + 1], al[mi], b1);
                    }
                }
                // Bl: consumed by Ah
                ldsm_x4(r0, r1, r2, r3, sb + SM_BL + swz(row, chunk));
                {
                    uint32_t b0[2] = {r0, r2}, b1[2] = {r1, r3};
#pragma unroll
                    for (int mi = 0; mi < 2; mi++) {
                        mma16816(d[mi][2 * np], ah[mi], b0);
                        mma16816(d[mi][2 * np + 1], ah[mi], b1);
                    }
                }
            }
        }

        // ---- epilogue for this chunk ----
        const int mrow = m0 + wm * 32 + (lane >> 2);
        const int ncol = n0 + wn * 32 + (lane & 3) * 2;
#pragma unroll
        for (int mi = 0; mi < 2; mi++) {
#pragma unroll
            for (int ni = 0; ni < 4; ni++) {
                float b0 = 0.f, b1 = 0.f;
                if (has_bias) {
                    b0 = bias[ncol + ni * 8];
                    b1 = bias[ncol + ni * 8 + 1];
                }
                float* p0 = C + (size_t)(mrow + mi * 16) * ldc + ncol + ni * 8;
                float* p1 = C + (size_t)(mrow + mi * 16 + 8) * ldc + ncol + ni * 8;
                *(float2*)p0 = make_float2(d[mi][ni][0] + b0, d[mi][ni][1] + b1);
                *(float2*)p1 = make_float2(d[mi][ni][2] + b0, d[mi][ni][3] + b1);
            }
        }
    }
}

// ============================================================
// HMMA flash attention (R5-proven): one CTA per (b,h), 8 warps
//   Q/K hi/lo: [208 rows][32 d] bf16, row stride 80 B
//   Vt hi/lo:  [32 d][208 kk] bf16, row stride 432 B
// ============================================================
#define AQH 0
#define AQL 16640
#define AKH 33280
#define AKL 49920
#define AVTH 66560
#define AVTL 80384
#define ASPOS 94208
#define ACOLC (ASPOS + TAB * NH * 4)      // 105872
#define ATTN_SMEM (ACOLC + 208 * 4)       // 106704

template<int NSTART, int NT>
__device__ __forceinline__ void half_pass(
    uint32_t qh, uint32_t ql, uint32_t kh, uint32_t kl,
    uint32_t vth, uint32_t vtl,
    const float* __restrict__ spos, const int* __restrict__ colC,
    int m0, int h, int R0, int R1, int lane,
    float o[4][4], float& mo0, float& mo1, float& sum0, float& sum1)
{
    const int lrow = lane & 15, lhalf = lane >> 4;
    float S[NT][4];
#pragma unroll
    for (int j = 0; j < NT; j++)
#pragma unroll
        for (int q = 0; q < 4; q++) S[j][q] = 0.f;

    // ---- QK^T, 3 split terms ----
#pragma unroll
    for (int term = 0; term < 3; term++) {
        uint32_t Ab = (term == 1) ? ql : qh;
        uint32_t Bb = (term == 2) ? kl : kh;
#pragma unroll
        for (int k0 = 0; k0 < 2; k0++) {
            uint32_t a[4];
            ldsm_x4(a[0], a[1], a[2], a[3],
                    Ab + (uint32_t)((m0 + lrow) * 80 + (k0 * 2 + lhalf) * 16));
#pragma unroll
            for (int np = 0; np < NT / 2; np++) {
                uint32_t r0, r1, r2, r3;
                ldsm_x4(r0, r1, r2, r3,
                        Bb + (uint32_t)(((NSTART + 2 * np) * 8 + lrow) * 80
                                        + (k0 * 2 + lhalf) * 16));
                uint32_t b0[2] = {r0, r2}, b1[2] = {r1, r3};
                mma16816(S[2 * np], a, b0);
                mma16816(S[2 * np + 1], a, b1);
            }
        }
    }

    // ---- bias + mask + row max ----
    float ml0 = -1e30f, ml1 = -1e30f;
#pragma unroll
    for (int j = 0; j < NT; j++) {
        int c0 = (NSTART + j) * 8 + (lane & 3) * 2;
#pragma unroll
        for (int e = 0; e < 2; e++) {
            int c = c0 + e;
            if (c < NQ) {
                int C4 = colC[c];
                S[j][e]     += spos[((R0 - C4) << 2) + h];
                S[j][2 + e] += spos[((R1 - C4) << 2) + h];
            } else {
                S[j][e] = -1e30f;
                S[j][2 + e] = -1e30f;
            }
        }
        ml0 = fmaxf(ml0, fmaxf(S[j][0], S[j][1]));
        ml1 = fmaxf(ml1, fmaxf(S[j][2], S[j][3]));
    }
    ml0 = fmaxf(ml0, __shfl_xor_sync(0xffffffffu, ml0, 1));
    ml0 = fmaxf(ml0, __shfl_xor_sync(0xffffffffu, ml0, 2));
    ml1 = fmaxf(ml1, __shfl_xor_sync(0xffffffffu, ml1, 1));
    ml1 = fmaxf(ml1, __shfl_xor_sync(0xffffffffu, ml1, 2));
    float mn0 = fmaxf(mo0, ml0), mn1 = fmaxf(mo1, ml1);
    float f0 = __expf(mo0 - mn0), f1 = __expf(mo1 - mn1);
    mo0 = mn0; mo1 = mn1;
    sum0 *= f0; sum1 *= f1;
#pragma unroll
    for (int n = 0; n < 4; n++) {
        o[n][0] *= f0; o[n][1] *= f0;
        o[n][2] *= f1; o[n][3] *= f1;
    }

    // ---- P = exp(S-m) -> bf16 hi/lo frags; PV 3 split terms ----
#pragma unroll
    for (int t = 0; t < NT / 2; t++) {
        uint32_t ah[4], al[4];
#pragma unroll
        for (int jj = 0; jj < 2; jj++) {
            int j = 2 * t + jj;
            float p0 = __expf(S[j][0] - mn0);
            float p1 = __expf(S[j][1] - mn0);
            float p2 = __expf(S[j][2] - mn1);
            float p3 = __expf(S[j][3] - mn1);
            sum0 += p0 + p1; sum1 += p2 + p3;
            split2(p0, p1, ah[2 * jj], al[2 * jj]);
            split2(p2, p3, ah[2 * jj + 1], al[2 * jj + 1]);
        }
        int kchunk = NSTART + 2 * t + lhalf;
#pragma unroll
        for (int np = 0; np < 2; np++) {
            uint32_t r0, r1, r2, r3;
            ldsm_x4(r0, r1, r2, r3,
                    vth + (uint32_t)((np * 16 + lrow) * 432 + kchunk * 16));
            {
                uint32_t b0[2] = {r0, r2}, b1[2] = {r1, r3};
                mma16816(o[2 * np], ah, b0); mma16816(o[2 * np + 1], ah, b1);
                mma16816(o[2 * np], al, b0); mma16816(o[2 * np + 1], al, b1);
            }
            ldsm_x4(r0, r1, r2, r3,
                    vtl + (uint32_t)((np * 16 + lrow) * 432 + kchunk * 16));
            {
                uint32_t b0[2] = {r0, r2}, b1[2] = {r1, r3};
                mma16816(o[2 * np], ah, b0); mma16816(o[2 * np + 1], ah, b1);
            }
        }
    }
}

__global__ __launch_bounds__(256, 2) void fattn_kernel()
{
    extern __shared__ char smb[];
    const uint32_t sb = smem_u32(smb);
    float* spos = (float*)(smb + ASPOS);
    int* colC = (int*)(smb + ACOLC);
    const int b = blockIdx.x, h = blockIdx.y;
    const int tid = threadIdx.x;

    // ---- stage q*scale/k/v as bf16 hi/lo (+ Vt transposed) ----
    const float* base = g_qkv + (size_t)b * NQ * KVN + h * HD;
    for (int idx = tid; idx < 208 * 32; idx += 256) {
        int n = idx >> 5, d = idx & 31;
        float qv = 0.f, kv = 0.f, vv = 0.f;
        if (n < NQ) {
            const float* row = base + (size_t)n * KVN;
            qv = row[d] * SCALE;
            kv = row[128 + d];
            vv = row[256 + d];
        }
        __nv_bfloat16 qhb = __float2bfloat16(qv);
        __nv_bfloat16 qlb = __float2bfloat16(qv - __bfloat162float(qhb));
        __nv_bfloat16 khb = __float2bfloat16(kv);
        __nv_bfloat16 klb = __float2bfloat16(kv - __bfloat162float(khb));
        __nv_bfloat16 vhb = __float2bfloat16(vv);
        __nv_bfloat16 vlb = __float2bfloat16(vv - __bfloat162float(vhb));
        *(__nv_bfloat16*)(smb + AQH + n * 80 + d * 2) = qhb;
        *(__nv_bfloat16*)(smb + AQL + n * 80 + d * 2) = qlb;
        *(__nv_bfloat16*)(smb + AKH + n * 80 + d * 2) = khb;
        *(__nv_bfloat16*)(smb + AKL + n * 80 + d * 2) = klb;
        *(__nv_bfloat16*)(smb + AVTH + d * 432 + n * 2) = vhb;
        *(__nv_bfloat16*)(smb + AVTL + d * 432 + n * 2) = vlb;
    }
    for (int i = tid; i < TAB * NH; i += 256) spos[i] = g_pos[i];
    for (int c = tid; c < 208; c += 256)
        colC[c] = (c < NQ) ? (c / 14) * 27 + (c % 14) : 0;
    __syncthreads();

    const int w = tid >> 5, lane = tid & 31;
    for (int s = w; s < 13; s += 8) {
        const int m0 = s * 16;
        const int row0 = m0 + (lane >> 2), row1 = row0 + 8;
        const int rc0 = min(row0, NQ - 1), rc1 = min(row1, NQ - 1);
        const int R0 = (rc0 / 14) * 27 + rc0 % 14 + 364;
        const int R1 = (rc1 / 14) * 27 + rc1 % 14 + 364;

        float o[4][4];
#pragma unroll
        for (int n = 0; n < 4; n++)
#pragma unroll
            for (int q = 0; q < 4; q++) o[n][q] = 0.f;
        float mo0 = -1e30f, mo1 = -1e30f, sum0 = 0.f, sum1 = 0.f;

        half_pass<0, 14>(sb + AQH, sb + AQL, sb + AKH, sb + AKL,
                         sb + AVTH, sb + AVTL, spos, colC,
                         m0, h, R0, R1, lane, o, mo0, mo1, sum0, sum1);
        half_pass<14, 12>(sb + AQH, sb + AQL, sb + AKH, sb + AKL,
                          sb + AVTH, sb + AVTL, spos, colC,
                          m0, h, R0, R1, lane, o, mo0, mo1, sum0, sum1);

        sum0 += __shfl_xor_sync(0xffffffffu, sum0, 1);
        sum0 += __shfl_xor_sync(0xffffffffu, sum0, 2);
        sum1 += __shfl_xor_sync(0xffffffffu, sum1, 1);
        sum1 += __shfl_xor_sync(0xffffffffu, sum1, 2);
        float i0 = 1.f / sum0, i1 = 1.f / sum1;

#pragma unroll
        for (int n = 0; n < 4; n++) {
            int d0 = n * 8 + (lane & 3) * 2;
            if (row0 < NQ)
                *(float2*)&g_att[((size_t)b * NQ + row0) * CDIM + h * HD + d0] =
                    make_float2(o[n][0] * i0, o[n][1] * i0);
            if (row1 < NQ)
                *(float2*)&g_att[((size_t)b * NQ + row1) * CDIM + h * HD + d0] =
                    make_float2(o[n][2] * i1, o[n][3] * i1);
        }
    }
}

// ============================================================
// launch
// ============================================================
extern "C" void kernel_launch(void* const* d_in, const int* in_sizes, int n_in,
                              void* d_out, int out_size)
{
    const float* x     = (const float*)d_in[0];
    const float* wq    = (const float*)d_in[1];
    const float* wkv   = (const float*)d_in[2];
    const float* wproj = (const float*)d_in[3];
    const float* bproj = (const float*)d_in[4];
    const float* pp_w  = (const float*)d_in[5];
    const float* pp_b  = (const float*)d_in[6];
    const float* ln1_g = (const float*)d_in[7];
    const float* ln1_b = (const float*)d_in[8];
    const float* l1_w  = (const float*)d_in[9];
    const float* l1_b  = (const float*)d_in[10];
    const float* ln2_g = (const float*)d_in[11];
    const float* ln2_b = (const float*)d_in[12];
    const float* l2_w  = (const float*)d_in[13];
    const float* l2_b  = (const float*)d_in[14];
    const float* ln3_g = (const float*)d_in[15];
    const float* ln3_b = (const float*)d_in[16];
    const float* l3_w  = (const float*)d_in[17];
    const float* l3_b  = (const float*)d_in[18];
    float* out = (float*)d_out;

    cudaFuncSetAttribute(hmma_gemm_kernel,
                         cudaFuncAttributeMaxDynamicSharedMemorySize, GSMEM);
    cudaFuncSetAttribute(fattn_kernel,
                         cudaFuncAttributeMaxDynamicSharedMemorySize, ATTN_SMEM);

    pos_mlp_kernel<<<3, 256>>>(pp_w, pp_b, ln1_g, ln1_b, l1_w, l1_b,
                               ln2_g, ln2_b, l2_w, l2_b,
                               ln3_g, ln3_b, l3_w, l3_b);

    wprep_kernel<<<256, 256>>>(wq, wkv, wproj);

    // QKV: x @ [wq|wkv] -> g_qkv (fp32)
    hmma_gemm_kernel<<<MTOT / 128, 256, GSMEM>>>(0, x, nullptr, nullptr);

    // flash attention -> g_att (fp32)
    fattn_kernel<<<dim3(BATCH, NH), 256, ATTN_SMEM>>>();

    // Proj: g_att @ wproj + bproj -> out (fp32)
    hmma_gemm_kernel<<<MTOT / 128, 256, GSMEM>>>(1, nullptr, out, bproj);
}

// round 8
// speedup vs baseline: 1.2941x; 1.0436x over previous
#include <cuda_runtime.h>
#include <cuda_bf16.h>
#include <math.h>
#include <stdint.h>

#define GS    14
#define NQ    196            // GS*GS
#define CDIM  128
#define NH    4
#define HD    32
#define BATCH 1024
#define MTOT  (BATCH * NQ)   // 200704
#define KVN   384            // q(128) | k(128) | v(128)
#define TAB   729            // (2*GS-1)^2
#define NCP   208            // padded col count
#define SCALE 0.17677669529663688f   // 32^-0.5

// ---- scratch (static device allocations; no cudaMalloc allowed) ----
__device__ float g_qkv[(size_t)MTOT * KVN];   // ~308 MB
__device__ float g_att[(size_t)MTOT * CDIM];  // ~103 MB
__device__ float g_pos[TAB * NH];
__device__ float g_bias[NH * NQ * NCP];       // precomputed rpb, cols padded w/ -1e30
__device__ __nv_bfloat16 g_wqkv_h[KVN * CDIM];   // [n=384][k=128]
__device__ __nv_bfloat16 g_wqkv_l[KVN * CDIM];
__device__ __nv_bfloat16 g_wp_h[CDIM * CDIM];    // [n=128][k=128]
__device__ __nv_bfloat16 g_wp_l[CDIM * CDIM];

// ============================================================
// helpers
// ============================================================
__device__ __forceinline__ uint32_t smem_u32(const void* p) {
    uint32_t a;
    asm("{ .reg .u64 t; cvta.to.shared.u64 t, %1; cvt.u32.u64 %0, t; }"
        : "=r"(a) : "l"(p));
    return a;
}
__device__ __forceinline__ void ldsm_x4(uint32_t& r0, uint32_t& r1,
                                        uint32_t& r2, uint32_t& r3, uint32_t addr) {
    asm volatile("ldmatrix.sync.aligned.m8n8.x4.shared.b16 {%0,%1,%2,%3}, [%4];"
                 : "=r"(r0), "=r"(r1), "=r"(r2), "=r"(r3) : "r"(addr));
}
__device__ __forceinline__ void mma16816(float* d, const uint32_t* a, const uint32_t* b) {
    asm volatile("mma.sync.aligned.m16n8k16.row.col.f32.bf16.bf16.f32 "
                 "{%0,%1,%2,%3}, {%4,%5,%6,%7}, {%8,%9}, {%0,%1,%2,%3};"
                 : "+f"(d[0]), "+f"(d[1]), "+f"(d[2]), "+f"(d[3])
                 : "r"(a[0]), "r"(a[1]), "r"(a[2]), "r"(a[3]),
                   "r"(b[0]), "r"(b[1]));
}
__device__ __forceinline__ void split2(float v0, float v1, uint32_t& hi, uint32_t& lo) {
    __nv_bfloat16 h0 = __float2bfloat16(v0), h1 = __float2bfloat16(v1);
    __nv_bfloat162 H = __halves2bfloat162(h0, h1);
    __nv_bfloat162 L = __halves2bfloat162(
        __float2bfloat16(v0 - __bfloat162float(h0)),
        __float2bfloat16(v1 - __bfloat162float(h1)));
    hi = *(uint32_t*)&H;
    lo = *(uint32_t*)&L;
}
// swizzled byte offset inside a [rows]x128 bf16 tile (256B rows, 16B chunks)
__device__ __forceinline__ uint32_t swz(int row, int chunk) {
    return (uint32_t)(row * 256 + ((chunk ^ (row & 7)) << 4));
}

// ============================================================
// Kernel 1: dynamic position-bias MLP (729 rows, tiny)
// ============================================================
__device__ __forceinline__ void ln_relu8(float* x, const float* g, const float* b) {
    float mu = 0.f;
#pragma unroll
    for (int d = 0; d < 8; d++) mu += x[d];
    mu *= 0.125f;
    float var = 0.f;
#pragma unroll
    for (int d = 0; d < 8; d++) { float t = x[d] - mu; var += t * t; }
    var *= 0.125f;
    float inv = rsqrtf(var + 1e-5f);
#pragma unroll
    for (int d = 0; d < 8; d++) {
        float t = (x[d] - mu) * inv * g[d] + b[d];
        x[d] = t > 0.f ? t : 0.f;
    }
}

__global__ void pos_mlp_kernel(
    const float* __restrict__ pp_w, const float* __restrict__ pp_b,
    const float* __restrict__ ln1_g, const float* __restrict__ ln1_b,
    const float* __restrict__ l1_w,  const float* __restrict__ l1_b,
    const float* __restrict__ ln2_g, const float* __restrict__ ln2_b,
    const float* __restrict__ l2_w,  const float* __restrict__ l2_b,
    const float* __restrict__ ln3_g, const float* __restrict__ ln3_b,
    const float* __restrict__ l3_w,  const float* __restrict__ l3_b)
{
    int m = blockIdx.x * blockDim.x + threadIdx.x;
    if (m >= TAB) return;
    float bi = (float)(m / 27 - 13);
    float bj = (float)(m % 27 - 13);
    float h[8], t[8];
#pragma unroll
    for (int d = 0; d < 8; d++) h[d] = bi * pp_w[d] + bj * pp_w[8 + d] + pp_b[d];
    ln_relu8(h, ln1_g, ln1_b);
#pragma unroll
    for (int j = 0; j < 8; j++) {
        float a = l1_b[j];
#pragma unroll
        for (int d = 0; d < 8; d++) a += h[d] * l1_w[d * 8 + j];
        t[j] = a;
    }
    ln_relu8(t, ln2_g, ln2_b);
#pragma unroll
    for (int j = 0; j < 8; j++) {
        float a = l2_b[j];
#pragma unroll
        for (int d = 0; d < 8; d++) a += t[d] * l2_w[d * 8 + j];
        h[j] = a;
    }
    ln_relu8(h, ln3_g, ln3_b);
#pragma unroll
    for (int j = 0; j < NH; j++) {
        float a = l3_b[j];
#pragma unroll
        for (int d = 0; d < 8; d++) a += h[d] * l3_w[d * NH + j];
        g_pos[m * NH + j] = a;
    }
}

// ============================================================
// Kernel 1b: expand rpb table -> full bias matrix per head
//   g_bias[h][q][c] = g_pos[rel_idx(q,c)*NH + h], c>=196 -> -1e30
// ============================================================
__global__ __launch_bounds__(256) void bias_prep_kernel()
{
    int idx = blockIdx.x * 256 + threadIdx.x;
    if (idx >= NH * NQ * NCP) return;
    int c = idx % NCP;
    int q = (idx / NCP) % NQ;
    int h = idx / (NCP * NQ);
    float v = -1e30f;
    if (c < NQ) {
        int qi = q / GS, qj = q - qi * GS;
        int ki = c / GS, kj = c - ki * GS;
        int t = (qi - ki + GS - 1) * 27 + (qj - kj + GS - 1);
        v = g_pos[t * NH + h];
    }
    g_bias[idx] = v;
}

// ============================================================
// Kernel: weight prep — transpose to [n][k], bf16 hi/lo split
// ============================================================
__global__ __launch_bounds__(256) void wprep_kernel(
    const float* __restrict__ wq, const float* __restrict__ wkv,
    const float* __restrict__ wproj)
{
    int idx = blockIdx.x * 256 + threadIdx.x;
    if (idx < KVN * CDIM) {
        int n = idx >> 7, k = idx & 127;
        float v = (n < 128) ? wq[k * 128 + n] : wkv[k * 256 + (n - 128)];
        __nv_bfloat16 h = __float2bfloat16(v);
        g_wqkv_h[idx] = h;
        g_wqkv_l[idx] = __float2bfloat16(v - __bfloat162float(h));
    } else if (idx < KVN * CDIM + CDIM * CDIM) {
        int j = idx - KVN * CDIM;
        int n = j >> 7, k = j & 127;
        float v = wproj[k * 128 + n];
        __nv_bfloat16 h = __float2bfloat16(v);
        g_wp_h[j] = h;
        g_wp_l[j] = __float2bfloat16(v - __bfloat162float(h));
    }
}

// ============================================================
// Kernel: HMMA GEMM, 3-term split, B chunked (R7-proven, 2 CTAs/SM)
// ============================================================
#define SM_AH 0
#define SM_AL 32768
#define SM_BH 65536
#define SM_BL 81920
#define GSMEM 98304

__global__ __launch_bounds__(256, 2) void hmma_gemm_kernel(
    int mode, const float* __restrict__ Ain,
    float* __restrict__ Cout, const float* __restrict__ bias)
{
    extern __shared__ char smc[];
    const uint32_t sb = smem_u32(smc);
    const int tid = threadIdx.x;
    const int w = tid >> 5, lane = tid & 31;
    const int m0 = blockIdx.x * 128;

    const float* A = (mode == 0) ? Ain : g_att;
    float* C = (mode == 0) ? g_qkv : Cout;
    const __nv_bfloat16* Bh = (mode == 0) ? g_wqkv_h : g_wp_h;
    const __nv_bfloat16* Bl = (mode == 0) ? g_wqkv_l : g_wp_l;
    const int NCH = (mode == 0) ? 6 : 2;
    const int ldc = (mode == 0) ? KVN : CDIM;
    const bool has_bias = (mode == 1);

    for (int idx = tid; idx < 2048; idx += 256) {
        int row = idx >> 4, c = idx & 15;
        const float* src = A + (size_t)(m0 + row) * CDIM + c * 8;
        float4 v0 = *(const float4*)src;
        float4 v1 = *(const float4*)(src + 4);
        float f[8] = {v0.x, v0.y, v0.z, v0.w, v1.x, v1.y, v1.z, v1.w};
        uint32_t hp[4], lp[4];
#pragma unroll
        for (int q = 0; q < 4; q++)
            split2(f[2 * q], f[2 * q + 1], hp[q], lp[q]);
        uint32_t off = swz(row, c);
        *(uint4*)(smc + SM_AH + off) = make_uint4(hp[0], hp[1], hp[2], hp[3]);
        *(uint4*)(smc + SM_AL + off) = make_uint4(lp[0], lp[1], lp[2], lp[3]);
    }

    const int wm = w >> 1;
    const int wn = w & 1;
    const int lrow = lane & 15;
    const int lchunk = lane >> 4;

    for (int ch = 0; ch < NCH; ch++) {
        const int n0 = ch * 64;
        __syncthreads();

        for (int idx = tid; idx < 1024; idx += 256) {
            int row = idx >> 4, c = idx & 15;
            size_t gi = (size_t)(n0 + row) * CDIM + c * 8;
            uint32_t off = swz(row, c);
            *(uint4*)(smc + SM_BH + off) = *(const uint4*)(Bh + gi);
            *(uint4*)(smc + SM_BL + off) = *(const uint4*)(Bl + gi);
        }
        __syncthreads();

        float d[2][4][4];
#pragma unroll
        for (int mi = 0; mi < 2; mi++)
#pragma unroll
            for (int ni = 0; ni < 4; ni++)
#pragma unroll
                for (int q = 0; q < 4; q++) d[mi][ni][q] = 0.f;

#pragma unroll
        for (int ks = 0; ks < 8; ks++) {
            const int chunk = ks * 2 + lchunk;
            uint32_t ah[2][4], al[2][4];
#pragma unroll
            for (int mi = 0; mi < 2; mi++) {
                int row = wm * 32 + mi * 16 + lrow;
                ldsm_x4(ah[mi][0], ah[mi][1], ah[mi][2], ah[mi][3],
                        sb + SM_AH + swz(row, chunk));
                ldsm_x4(al[mi][0], al[mi][1], al[mi][2], al[mi][3],
                        sb + SM_AL + swz(row, chunk));
            }
#pragma unroll
            for (int np = 0; np < 2; np++) {
                int row = wn * 32 + np * 16 + lrow;
                uint32_t r0, r1, r2, r3;
                ldsm_x4(r0, r1, r2, r3, sb + SM_BH + swz(row, chunk));
                {
                    uint32_t b0[2] = {r0, r2}, b1[2] = {r1, r3};
#pragma unroll
                    for (int mi = 0; mi < 2; mi++) {
                        mma16816(d[mi][2 * np], ah[mi], b0);
                        mma16816(d[mi][2 * np + 1], ah[mi], b1);
                        mma16816(d[mi][2 * np], al[mi], b0);
                        mma16816(d[mi][2 * np + 1], al[mi], b1);
                    }
                }
                ldsm_x4(r0, r1, r2, r3, sb + SM_BL + swz(row, chunk));
                {
                    uint32_t b0[2] = {r0, r2}, b1[2] = {r1, r3};
#pragma unroll
                    for (int mi = 0; mi < 2; mi++) {
                        mma16816(d[mi][2 * np], ah[mi], b0);
                        mma16816(d[mi][2 * np + 1], ah[mi], b1);
                    }
                }
            }
        }

        const int mrow = m0 + wm * 32 + (lane >> 2);
        const int ncol = n0 + wn * 32 + (lane & 3) * 2;
#pragma unroll
        for (int mi = 0; mi < 2; mi++) {
#pragma unroll
            for (int ni = 0; ni < 4; ni++) {
                float b0 = 0.f, b1 = 0.f;
                if (has_bias) {
                    b0 = bias[ncol + ni * 8];
                    b1 = bias[ncol + ni * 8 + 1];
                }
                float* p0 = C + (size_t)(mrow + mi * 16) * ldc + ncol + ni * 8;
                float* p1 = C + (size_t)(mrow + mi * 16 + 8) * ldc + ncol + ni * 8;
                *(float2*)p0 = make_float2(d[mi][ni][0] + b0, d[mi][ni][1] + b1);
                *(float2*)p1 = make_float2(d[mi][ni][2] + b0, d[mi][ni][3] + b1);
            }
        }
    }
}

// ============================================================
// HMMA flash attention: one CTA per (b,h), 8 warps
//   bias via precomputed g_bias rows (vectorized L2 loads, mask folded in)
// ============================================================
#define AQH 0
#define AQL 16640
#define AKH 33280
#define AKL 49920
#define AVTH 66560
#define AVTL 80384
#define ATTN_SMEM 94208

template<int NSTART, int NT>
__device__ __forceinline__ void half_pass(
    uint32_t qh, uint32_t ql, uint32_t kh, uint32_t kl,
    uint32_t vth, uint32_t vtl,
    const float* __restrict__ bias0, const float* __restrict__ bias1,
    int m0, int lane,
    float o[4][4], float& mo0, float& mo1, float& sum0, float& sum1)
{
    const int lrow = lane & 15, lhalf = lane >> 4;
    float S[NT][4];
#pragma unroll
    for (int j = 0; j < NT; j++)
#pragma unroll
        for (int q = 0; q < 4; q++) S[j][q] = 0.f;

    // ---- QK^T, 3 split terms ----
#pragma unroll
    for (int term = 0; term < 3; term++) {
        uint32_t Ab = (term == 1) ? ql : qh;
        uint32_t Bb = (term == 2) ? kl : kh;
#pragma unroll
        for (int k0 = 0; k0 < 2; k0++) {
            uint32_t a[4];
            ldsm_x4(a[0], a[1], a[2], a[3],
                    Ab + (uint32_t)((m0 + lrow) * 80 + (k0 * 2 + lhalf) * 16));
#pragma unroll
            for (int np = 0; np < NT / 2; np++) {
                uint32_t r0, r1, r2, r3;
                ldsm_x4(r0, r1, r2, r3,
                        Bb + (uint32_t)(((NSTART + 2 * np) * 8 + lrow) * 80
                                        + (k0 * 2 + lhalf) * 16));
                uint32_t b0[2] = {r0, r2}, b1[2] = {r1, r3};
                mma16816(S[2 * np], a, b0);
                mma16816(S[2 * np + 1], a, b1);
            }
        }
    }

    // ---- bias (mask pre-folded) + row max ----
    float ml0 = -1e30f, ml1 = -1e30f;
#pragma unroll
    for (int j = 0; j < NT; j++) {
        float2 v0 = *(const float2*)(bias0 + NSTART * 8 + j * 8);
        float2 v1 = *(const float2*)(bias1 + NSTART * 8 + j * 8);
        S[j][0] += v0.x; S[j][1] += v0.y;
        S[j][2] += v1.x; S[j][3] += v1.y;
        ml0 = fmaxf(ml0, fmaxf(S[j][0], S[j][1]));
        ml1 = fmaxf(ml1, fmaxf(S[j][2], S[j][3]));
    }
    ml0 = fmaxf(ml0, __shfl_xor_sync(0xffffffffu, ml0, 1));
    ml0 = fmaxf(ml0, __shfl_xor_sync(0xffffffffu, ml0, 2));
    ml1 = fmaxf(ml1, __shfl_xor_sync(0xffffffffu, ml1, 1));
    ml1 = fmaxf(ml1, __shfl_xor_sync(0xffffffffu, ml1, 2));
    float mn0 = fmaxf(mo0, ml0), mn1 = fmaxf(mo1, ml1);
    float f0 = __expf(mo0 - mn0), f1 = __expf(mo1 - mn1);
    mo0 = mn0; mo1 = mn1;
    sum0 *= f0; sum1 *= f1;
#pragma unroll
    for (int n = 0; n < 4; n++) {
        o[n][0] *= f0; o[n][1] *= f0;
        o[n][2] *= f1; o[n][3] *= f1;
    }

    // ---- P = exp(S-m) -> bf16 hi/lo frags; PV 3 split terms ----
#pragma unroll
    for (int t = 0; t < NT / 2; t++) {
        uint32_t ah[4], al[4];
#pragma unroll
        for (int jj = 0; jj < 2; jj++) {
            int j = 2 * t + jj;
            float p0 = __expf(S[j][0] - mn0);
            float p1 = __expf(S[j][1] - mn0);
            float p2 = __expf(S[j][2] - mn1);
            float p3 = __expf(S[j][3] - mn1);
            sum0 += p0 + p1; sum1 += p2 + p3;
            split2(p0, p1, ah[2 * jj], al[2 * jj]);
            split2(p2, p3, ah[2 * jj + 1], al[2 * jj + 1]);
        }
        int kchunk = NSTART + 2 * t + lhalf;
#pragma unroll
        for (int np = 0; np < 2; np++) {
            uint32_t r0, r1, r2, r3;
            ldsm_x4(r0, r1, r2, r3,
                    vth + (uint32_t)((np * 16 + lrow) * 432 + kchunk * 16));
            {
                uint32_t b0[2] = {r0, r2}, b1[2] = {r1, r3};
                mma16816(o[2 * np], ah, b0); mma16816(o[2 * np + 1], ah, b1);
                mma16816(o[2 * np], al, b0); mma16816(o[2 * np + 1], al, b1);
            }
            ldsm_x4(r0, r1, r2, r3,
                    vtl + (uint32_t)((np * 16 + lrow) * 432 + kchunk * 16));
            {
                uint32_t b0[2] = {r0, r2}, b1[2] = {r1, r3};
                mma16816(o[2 * np], ah, b0); mma16816(o[2 * np + 1], ah, b1);
            }
        }
    }
}

__global__ __launch_bounds__(256, 2) void fattn_kernel()
{
    extern __shared__ char smb[];
    const uint32_t sb = smem_u32(smb);
    const int b = blockIdx.x, h = blockIdx.y;
    const int tid = threadIdx.x;

    // ---- stage q*scale/k/v as bf16 hi/lo (+ Vt transposed) ----
    const float* base = g_qkv + (size_t)b * NQ * KVN + h * HD;
    for (int idx = tid; idx < 208 * 32; idx += 256) {
        int n = idx >> 5, d = idx & 31;
        float qv = 0.f, kv = 0.f, vv = 0.f;
        if (n < NQ) {
            const float* row = base + (size_t)n * KVN;
            qv = row[d] * SCALE;
            kv = row[128 + d];
            vv = row[256 + d];
        }
        __nv_bfloat16 qhb = __float2bfloat16(qv);
        __nv_bfloat16 qlb = __float2bfloat16(qv - __bfloat162float(qhb));
        __nv_bfloat16 khb = __float2bfloat16(kv);
        __nv_bfloat16 klb = __float2bfloat16(kv - __bfloat162float(khb));
        __nv_bfloat16 vhb = __float2bfloat16(vv);
        __nv_bfloat16 vlb = __float2bfloat16(vv - __bfloat162float(vhb));
        *(__nv_bfloat16*)(smb + AQH + n * 80 + d * 2) = qhb;
        *(__nv_bfloat16*)(smb + AQL + n * 80 + d * 2) = qlb;
        *(__nv_bfloat16*)(smb + AKH + n * 80 + d * 2) = khb;
        *(__nv_bfloat16*)(smb + AKL + n * 80 + d * 2) = klb;
        *(__nv_bfloat16*)(smb + AVTH + d * 432 + n * 2) = vhb;
        *(__nv_bfloat16*)(smb + AVTL + d * 432 + n * 2) = vlb;
    }
    __syncthreads();

    const int w = tid >> 5, lane = tid & 31;
    for (int s = w; s < 13; s += 8) {
        const int m0 = s * 16;
        const int row0 = m0 + (lane >> 2), row1 = row0 + 8;
        const int rc0 = min(row0, NQ - 1), rc1 = min(row1, NQ - 1);
        const float* bias0 = g_bias + ((size_t)h * NQ + rc0) * NCP + (lane & 3) * 2;
        const float* bias1 = g_bias + ((size_t)h * NQ + rc1) * NCP + (lane & 3) * 2;

        float o[4][4];
#pragma unroll
        for (int n = 0; n < 4; n++)
#pragma unroll
            for (int q = 0; q < 4; q++) o[n][q] = 0.f;
        float mo0 = -1e30f, mo1 = -1e30f, sum0 = 0.f, sum1 = 0.f;

        half_pass<0, 14>(sb + AQH, sb + AQL, sb + AKH, sb + AKL,
                         sb + AVTH, sb + AVTL, bias0, bias1,
                         m0, lane, o, mo0, mo1, sum0, sum1);
        half_pass<14, 12>(sb + AQH, sb + AQL, sb + AKH, sb + AKL,
                          sb + AVTH, sb + AVTL, bias0, bias1,
                          m0, lane, o, mo0, mo1, sum0, sum1);

        sum0 += __shfl_xor_sync(0xffffffffu, sum0, 1);
        sum0 += __shfl_xor_sync(0xffffffffu, sum0, 2);
        sum1 += __shfl_xor_sync(0xffffffffu, sum1, 1);
        sum1 += __shfl_xor_sync(0xffffffffu, sum1, 2);
        float i0 = 1.f / sum0, i1 = 1.f / sum1;

#pragma unroll
        for (int n = 0; n < 4; n++) {
            int d0 = n * 8 + (lane & 3) * 2;
            if (row0 < NQ)
                *(float2*)&g_att[((size_t)b * NQ + row0) * CDIM + h * HD + d0] =
                    make_float2(o[n][0] * i0, o[n][1] * i0);
            if (row1 < NQ)
                *(float2*)&g_att[((size_t)b * NQ + row1) * CDIM + h * HD + d0] =
                    make_float2(o[n][2] * i1, o[n][3] * i1);
        }
    }
}

// ============================================================
// launch
// ============================================================
extern "C" void kernel_launch(void* const* d_in, const int* in_sizes, int n_in,
                              void* d_out, int out_size)
{
    const float* x     = (const float*)d_in[0];
    const float* wq    = (const float*)d_in[1];
    const float* wkv   = (const float*)d_in[2];
    const float* wproj = (const float*)d_in[3];
    const float* bproj = (const float*)d_in[4];
    const float* pp_w  = (const float*)d_in[5];
    const float* pp_b  = (const float*)d_in[6];
    const float* ln1_g = (const float*)d_in[7];
    const float* ln1_b = (const float*)d_in[8];
    const float* l1_w  = (const float*)d_in[9];
    const float* l1_b  = (const float*)d_in[10];
    const float* ln2_g = (const float*)d_in[11];
    const float* ln2_b = (const float*)d_in[12];
    const float* l2_w  = (const float*)d_in[13];
    const float* l2_b  = (const float*)d_in[14];
    const float* ln3_g = (const float*)d_in[15];
    const float* ln3_b = (const float*)d_in[16];
    const float* l3_w  = (const float*)d_in[17];
    const float* l3_b  = (const float*)d_in[18];
    float* out = (float*)d_out;

    cudaFuncSetAttribute(hmma_gemm_kernel,
                         cudaFuncAttributeMaxDynamicSharedMemorySize, GSMEM);
    cudaFuncSetAttribute(fattn_kernel,
                         cudaFuncAttributeMaxDynamicSharedMemorySize, ATTN_SMEM);

    pos_mlp_kernel<<<3, 256>>>(pp_w, pp_b, ln1_g, ln1_b, l1_w, l1_b,
                               ln2_g, ln2_b, l2_w, l2_b,
                               ln3_g, ln3_b, l3_w, l3_b);

    bias_prep_kernel<<<(NH * NQ * NCP + 255) / 256, 256>>>();

    wprep_kernel<<<256, 256>>>(wq, wkv, wproj);

    // QKV: x @ [wq|wkv] -> g_qkv (fp32)
    hmma_gemm_kernel<<<MTOT / 128, 256, GSMEM>>>(0, x, nullptr, nullptr);

    // flash attention -> g_att (fp32)
    fattn_kernel<<<dim3(BATCH, NH), 256, ATTN_SMEM>>>();

    // Proj: g_att @ wproj + bproj -> out (fp32)
    hmma_gemm_kernel<<<MTOT / 128, 256, GSMEM>>>(1, nullptr, out, bproj);
}

// round 9
// speedup vs baseline: 1.5055x; 1.1634x over previous
#include <cuda_runtime.h>
#include <cuda_bf16.h>
#include <cuda_fp16.h>
#include <math.h>
#include <stdint.h>

#define GS    14
#define NQ    196            // GS*GS
#define CDIM  128
#define NH    4
#define HD    32
#define BATCH 1024
#define MTOT  (BATCH * NQ)   // 200704
#define KVN   384            // q(128) | k(128) | v(128)
#define TAB   729            // (2*GS-1)^2
#define NCP   208            // padded col count
#define SCALE 0.17677669529663688f   // 32^-0.5

// ---- scratch (static device allocations; no cudaMalloc allowed) ----
__device__ float g_qkv[(size_t)MTOT * KVN];   // ~308 MB
__device__ float g_att[(size_t)MTOT * CDIM];  // ~103 MB
__device__ float g_pos[TAB * NH];
__device__ float g_bias[NH * NQ * NCP];       // precomputed rpb, cols padded w/ -1e30
__device__ __nv_bfloat16 g_wqkv_h[KVN * CDIM];   // [n=384][k=128]
__device__ __nv_bfloat16 g_wqkv_l[KVN * CDIM];
__device__ __nv_bfloat16 g_wp_h[CDIM * CDIM];    // [n=128][k=128]
__device__ __nv_bfloat16 g_wp_l[CDIM * CDIM];

// ============================================================
// helpers
// ============================================================
__device__ __forceinline__ uint32_t smem_u32(const void* p) {
    uint32_t a;
    asm("{ .reg .u64 t; cvta.to.shared.u64 t, %1; cvt.u32.u64 %0, t; }"
        : "=r"(a) : "l"(p));
    return a;
}
__device__ __forceinline__ void ldsm_x4(uint32_t& r0, uint32_t& r1,
                                        uint32_t& r2, uint32_t& r3, uint32_t addr) {
    asm volatile("ldmatrix.sync.aligned.m8n8.x4.shared.b16 {%0,%1,%2,%3}, [%4];"
                 : "=r"(r0), "=r"(r1), "=r"(r2), "=r"(r3) : "r"(addr));
}
// bf16 mma (GEMMs)
__device__ __forceinline__ void mma16816(float* d, const uint32_t* a, const uint32_t* b) {
    asm volatile("mma.sync.aligned.m16n8k16.row.col.f32.bf16.bf16.f32 "
                 "{%0,%1,%2,%3}, {%4,%5,%6,%7}, {%8,%9}, {%0,%1,%2,%3};"
                 : "+f"(d[0]), "+f"(d[1]), "+f"(d[2]), "+f"(d[3])
                 : "r"(a[0]), "r"(a[1]), "r"(a[2]), "r"(a[3]),
                   "r"(b[0]), "r"(b[1]));
}
// fp16 mma (attention)
__device__ __forceinline__ void mma16816h(float* d, const uint32_t* a, const uint32_t* b) {
    asm volatile("mma.sync.aligned.m16n8k16.row.col.f32.f16.f16.f32 "
                 "{%0,%1,%2,%3}, {%4,%5,%6,%7}, {%8,%9}, {%0,%1,%2,%3};"
                 : "+f"(d[0]), "+f"(d[1]), "+f"(d[2]), "+f"(d[3])
                 : "r"(a[0]), "r"(a[1]), "r"(a[2]), "r"(a[3]),
                   "r"(b[0]), "r"(b[1]));
}
__device__ __forceinline__ void split2(float v0, float v1, uint32_t& hi, uint32_t& lo) {
    __nv_bfloat16 h0 = __float2bfloat16(v0), h1 = __float2bfloat16(v1);
    __nv_bfloat162 H = __halves2bfloat162(h0, h1);
    __nv_bfloat162 L = __halves2bfloat162(
        __float2bfloat16(v0 - __bfloat162float(h0)),
        __float2bfloat16(v1 - __bfloat162float(h1)));
    hi = *(uint32_t*)&H;
    lo = *(uint32_t*)&L;
}
__device__ __forceinline__ uint32_t pack2h(float v0, float v1) {
    __half2 H = __halves2half2(__float2half(v0), __float2half(v1));
    return *(uint32_t*)&H;
}
// swizzled byte offset inside a [rows]x128 bf16 tile (256B rows, 16B chunks)
__device__ __forceinline__ uint32_t swz(int row, int chunk) {
    return (uint32_t)(row * 256 + ((chunk ^ (row & 7)) << 4));
}
__device__ __forceinline__ void cpasync16(uint32_t saddr, const void* g) {
    asm volatile("cp.async.cg.shared.global [%0], [%1], 16;"
                 :: "r"(saddr), "l"(g));
}

// ============================================================
// Kernel 1: dynamic position-bias MLP (729 rows, tiny)
// ============================================================
__device__ __forceinline__ void ln_relu8(float* x, const float* g, const float* b) {
    float mu = 0.f;
#pragma unroll
    for (int d = 0; d < 8; d++) mu += x[d];
    mu *= 0.125f;
    float var = 0.f;
#pragma unroll
    for (int d = 0; d < 8; d++) { float t = x[d] - mu; var += t * t; }
    var *= 0.125f;
    float inv = rsqrtf(var + 1e-5f);
#pragma unroll
    for (int d = 0; d < 8; d++) {
        float t = (x[d] - mu) * inv * g[d] + b[d];
        x[d] = t > 0.f ? t : 0.f;
    }
}

__global__ void pos_mlp_kernel(
    const float* __restrict__ pp_w, const float* __restrict__ pp_b,
    const float* __restrict__ ln1_g, const float* __restrict__ ln1_b,
    const float* __restrict__ l1_w,  const float* __restrict__ l1_b,
    const float* __restrict__ ln2_g, const float* __restrict__ ln2_b,
    const float* __restrict__ l2_w,  const float* __restrict__ l2_b,
    const float* __restrict__ ln3_g, const float* __restrict__ ln3_b,
    const float* __restrict__ l3_w,  const float* __restrict__ l3_b)
{
    int m = blockIdx.x * blockDim.x + threadIdx.x;
    if (m >= TAB) return;
    float bi = (float)(m / 27 - 13);
    float bj = (float)(m % 27 - 13);
    float h[8], t[8];
#pragma unroll
    for (int d = 0; d < 8; d++) h[d] = bi * pp_w[d] + bj * pp_w[8 + d] + pp_b[d];
    ln_relu8(h, ln1_g, ln1_b);
#pragma unroll
    for (int j = 0; j < 8; j++) {
        float a = l1_b[j];
#pragma unroll
        for (int d = 0; d < 8; d++) a += h[d] * l1_w[d * 8 + j];
        t[j] = a;
    }
    ln_relu8(t, ln2_g, ln2_b);
#pragma unroll
    for (int j = 0; j < 8; j++) {
        float a = l2_b[j];
#pragma unroll
        for (int d = 0; d < 8; d++) a += t[d] * l2_w[d * 8 + j];
        h[j] = a;
    }
    ln_relu8(h, ln3_g, ln3_b);
#pragma unroll
    for (int j = 0; j < NH; j++) {
        float a = l3_b[j];
#pragma unroll
        for (int d = 0; d < 8; d++) a += h[d] * l3_w[d * NH + j];
        g_pos[m * NH + j] = a;
    }
}

// ============================================================
// Kernel 1b: expand rpb table -> full bias matrix per head
// ============================================================
__global__ __launch_bounds__(256) void bias_prep_kernel()
{
    int idx = blockIdx.x * 256 + threadIdx.x;
    if (idx >= NH * NQ * NCP) return;
    int c = idx % NCP;
    int q = (idx / NCP) % NQ;
    int h = idx / (NCP * NQ);
    float v = -1e30f;
    if (c < NQ) {
        int qi = q / GS, qj = q - qi * GS;
        int ki = c / GS, kj = c - ki * GS;
        int t = (qi - ki + GS - 1) * 27 + (qj - kj + GS - 1);
        v = g_pos[t * NH + h];
    }
    g_bias[idx] = v;
}

// ============================================================
// Kernel: weight prep — transpose to [n][k], bf16 hi/lo split
// ============================================================
__global__ __launch_bounds__(256) void wprep_kernel(
    const float* __restrict__ wq, const float* __restrict__ wkv,
    const float* __restrict__ wproj)
{
    int idx = blockIdx.x * 256 + threadIdx.x;
    if (idx < KVN * CDIM) {
        int n = idx >> 7, k = idx & 127;
        float v = (n < 128) ? wq[k * 128 + n] : wkv[k * 256 + (n - 128)];
        __nv_bfloat16 h = __float2bfloat16(v);
        g_wqkv_h[idx] = h;
        g_wqkv_l[idx] = __float2bfloat16(v - __bfloat162float(h));
    } else if (idx < KVN * CDIM + CDIM * CDIM) {
        int j = idx - KVN * CDIM;
        int n = j >> 7, k = j & 127;
        float v = wproj[k * 128 + n];
        __nv_bfloat16 h = __float2bfloat16(v);
        g_wp_h[j] = h;
        g_wp_l[j] = __float2bfloat16(v - __bfloat162float(h));
    }
}

// ============================================================
// Kernel: HMMA GEMM, 3-term split, 32-row B chunks with
//   cp.async double-buffering (2 CTAs/SM, 96KB smem)
// ============================================================
#define SM_AH 0
#define SM_AL 32768
#define SM_B  65536            // 2 buffers x 16KB (hi @ +0, lo @ +8192)
#define GSMEM 98304

__global__ __launch_bounds__(256, 2) void hmma_gemm_kernel(
    int mode, const float* __restrict__ Ain,
    float* __restrict__ Cout, const float* __restrict__ bias)
{
    extern __shared__ char smc[];
    const uint32_t sb = smem_u32(smc);
    const int tid = threadIdx.x;
    const int w = tid >> 5, lane = tid & 31;
    const int m0 = blockIdx.x * 128;

    const float* A = (mode == 0) ? Ain : g_att;
    float* C = (mode == 0) ? g_qkv : Cout;
    const __nv_bfloat16* Bh = (mode == 0) ? g_wqkv_h : g_wp_h;
    const __nv_bfloat16* Bl = (mode == 0) ? g_wqkv_l : g_wp_l;
    const int NCH = (mode == 0) ? 12 : 4;     // 32-row B chunks
    const int ldc = (mode == 0) ? KVN : CDIM;
    const bool has_bias = (mode == 1);

    // ---- stage A: fp32 -> bf16 hi/lo, swizzled smem (128 rows) ----
    for (int idx = tid; idx < 2048; idx += 256) {
        int row = idx >> 4, c = idx & 15;
        const float* src = A + (size_t)(m0 + row) * CDIM + c * 8;
        float4 v0 = *(const float4*)src;
        float4 v1 = *(const float4*)(src + 4);
        float f[8] = {v0.x, v0.y, v0.z, v0.w, v1.x, v1.y, v1.z, v1.w};
        uint32_t hp[4], lp[4];
#pragma unroll
        for (int q = 0; q < 4; q++)
            split2(f[2 * q], f[2 * q + 1], hp[q], lp[q]);
        uint32_t off = swz(row, c);
        *(uint4*)(smc + SM_AH + off) = make_uint4(hp[0], hp[1], hp[2], hp[3]);
        *(uint4*)(smc + SM_AL + off) = make_uint4(lp[0], lp[1], lp[2], lp[3]);
    }

    // prefetch chunk 0
    {
        for (int idx = tid; idx < 512; idx += 256) {
            int row = idx >> 4, c = idx & 15;
            uint32_t dst = sb + SM_B + swz(row, c);
            const size_t gi = (size_t)row * CDIM + c * 8;
            cpasync16(dst, Bh + gi);
            cpasync16(dst + 8192, Bl + gi);
        }
        asm volatile("cp.async.commit_group;");
    }

    const int wm = w >> 1;        // 0..3 -> 32 m-rows
    const int wn = w & 1;         // 0..1 -> 16 n-cols of the 32-col chunk
    const int lrow = lane & 15;
    const int lchunk = lane >> 4;

    for (int ch = 0; ch < NCH; ch++) {
        const int n0 = ch * 32;
        if (ch + 1 < NCH) {
            for (int idx = tid; idx < 512; idx += 256) {
                int row = idx >> 4, c = idx & 15;
                uint32_t dst = sb + SM_B + ((ch + 1) & 1) * 16384 + swz(row, c);
                const size_t gi = (size_t)(n0 + 32 + row) * CDIM + c * 8;
                cpasync16(dst, Bh + gi);
                cpasync16(dst + 8192, Bl + gi);
            }
            asm volatile("cp.async.commit_group;");
            asm volatile("cp.async.wait_group 1;");
        } else {
            asm volatile("cp.async.wait_group 0;");
        }
        __syncthreads();

        const uint32_t bb = sb + SM_B + (ch & 1) * 16384;

        float d[2][2][4];
#pragma unroll
        for (int mi = 0; mi < 2; mi++)
#pragma unroll
            for (int ni = 0; ni < 2; ni++)
#pragma unroll
                for (int q = 0; q < 4; q++) d[mi][ni][q] = 0.f;

#pragma unroll
        for (int ks = 0; ks < 8; ks++) {
            const int chunk = ks * 2 + lchunk;
            uint32_t ah[2][4], al[2][4];
#pragma unroll
            for (int mi = 0; mi < 2; mi++) {
                int row = wm * 32 + mi * 16 + lrow;
                ldsm_x4(ah[mi][0], ah[mi][1], ah[mi][2], ah[mi][3],
                        sb + SM_AH + swz(row, chunk));
                ldsm_x4(al[mi][0], al[mi][1], al[mi][2], al[mi][3],
                        sb + SM_AL + swz(row, chunk));
            }
            int brow = wn * 16 + lrow;
            uint32_t r0, r1, r2, r3;
            ldsm_x4(r0, r1, r2, r3, bb + swz(brow, chunk));
            {
                uint32_t b0[2] = {r0, r2}, b1[2] = {r1, r3};
#pragma unroll
                for (int mi = 0; mi < 2; mi++) {
                    mma16816(d[mi][0], ah[mi], b0);
                    mma16816(d[mi][1], ah[mi], b1);
                    mma16816(d[mi][0], al[mi], b0);
                    mma16816(d[mi][1], al[mi], b1);
                }
            }
            ldsm_x4(r0, r1, r2, r3, bb + 8192 + swz(brow, chunk));
            {
                uint32_t b0[2] = {r0, r2}, b1[2] = {r1, r3};
#pragma unroll
                for (int mi = 0; mi < 2; mi++) {
                    mma16816(d[mi][0], ah[mi], b0);
                    mma16816(d[mi][1], ah[mi], b1);
                }
            }
        }
        __syncthreads();   // compute done before next prefetch overwrites buffer

        const int mrow = m0 + wm * 32 + (lane >> 2);
        const int ncol = n0 + wn * 16 + (lane & 3) * 2;
#pragma unroll
        for (int mi = 0; mi < 2; mi++) {
#pragma unroll
            for (int ni = 0; ni < 2; ni++) {
                float b0 = 0.f, b1 = 0.f;
                if (has_bias) {
                    b0 = bias[ncol + ni * 8];
                    b1 = bias[ncol + ni * 8 + 1];
                }
                float* p0 = C + (size_t)(mrow + mi * 16) * ldc + ncol + ni * 8;
                float* p1 = C + (size_t)(mrow + mi * 16 + 8) * ldc + ncol + ni * 8;
                *(float2*)p0 = make_float2(d[mi][ni][0] + b0, d[mi][ni][1] + b1);
                *(float2*)p1 = make_float2(d[mi][ni][2] + b0, d[mi][ni][3] + b1);
            }
        }
    }
}

// ============================================================
// HMMA flash attention (fp16): one CTA per (b,h), 8 warps
//   Q/K hi/lo fp16: [208 rows][32 d], stride 80 B
//   Vt single fp16: [32 d][208 kk], stride 432 B
//   QK^T: 3-term fp16 split (err ~2^-23); PV: 1-term fp16 (err ~3e-4)
// ============================================================
#define AQH 0
#define AQL 16640
#define AKH 33280
#define AKL 49920
#define AVTH 66560
#define ATTN_SMEM 80384

template<int NSTART, int NT>
__device__ __forceinline__ void half_pass(
    uint32_t qh, uint32_t ql, uint32_t kh, uint32_t kl, uint32_t vth,
    const float* __restrict__ bias0, const float* __restrict__ bias1,
    int m0, int lane,
    float o[4][4], float& mo0, float& mo1, float& sum0, float& sum1)
{
    const int lrow = lane & 15, lhalf = lane >> 4;
    float S[NT][4];
#pragma unroll
    for (int j = 0; j < NT; j++)
#pragma unroll
        for (int q = 0; q < 4; q++) S[j][q] = 0.f;

    // ---- QK^T, 3 split terms (fp16) ----
#pragma unroll
    for (int term = 0; term < 3; term++) {
        uint32_t Ab = (term == 1) ? ql : qh;
        uint32_t Bb = (term == 2) ? kl : kh;
#pragma unroll
        for (int k0 = 0; k0 < 2; k0++) {
            uint32_t a[4];
            ldsm_x4(a[0], a[1], a[2], a[3],
                    Ab + (uint32_t)((m0 + lrow) * 80 + (k0 * 2 + lhalf) * 16));
#pragma unroll
            for (int np = 0; np < NT / 2; np++) {
                uint32_t r0, r1, r2, r3;
                ldsm_x4(r0, r1, r2, r3,
                        Bb + (uint32_t)(((NSTART + 2 * np) * 8 + lrow) * 80
                                        + (k0 * 2 + lhalf) * 16));
                uint32_t b0[2] = {r0, r2}, b1[2] = {r1, r3};
                mma16816h(S[2 * np], a, b0);
                mma16816h(S[2 * np + 1], a, b1);
            }
        }
    }

    // ---- bias (mask pre-folded) + row max ----
    float ml0 = -1e30f, ml1 = -1e30f;
#pragma unroll
    for (int j = 0; j < NT; j++) {
        float2 v0 = *(const float2*)(bias0 + NSTART * 8 + j * 8);
        float2 v1 = *(const float2*)(bias1 + NSTART * 8 + j * 8);
        S[j][0] += v0.x; S[j][1] += v0.y;
        S[j][2] += v1.x; S[j][3] += v1.y;
        ml0 = fmaxf(ml0, fmaxf(S[j][0], S[j][1]));
        ml1 = fmaxf(ml1, fmaxf(S[j][2], S[j][3]));
    }
    ml0 = fmaxf(ml0, __shfl_xor_sync(0xffffffffu, ml0, 1));
    ml0 = fmaxf(ml0, __shfl_xor_sync(0xffffffffu, ml0, 2));
    ml1 = fmaxf(ml1, __shfl_xor_sync(0xffffffffu, ml1, 1));
    ml1 = fmaxf(ml1, __shfl_xor_sync(0xffffffffu, ml1, 2));
    float mn0 = fmaxf(mo0, ml0), mn1 = fmaxf(mo1, ml1);
    float f0 = __expf(mo0 - mn0), f1 = __expf(mo1 - mn1);
    mo0 = mn0; mo1 = mn1;
    sum0 *= f0; sum1 *= f1;
#pragma unroll
    for (int n = 0; n < 4; n++) {
        o[n][0] *= f0; o[n][1] *= f0;
        o[n][2] *= f1; o[n][3] *= f1;
    }

    // ---- P = exp(S-m) -> fp16 frags; PV single term ----
#pragma unroll
    for (int t = 0; t < NT / 2; t++) {
        uint32_t ah[4];
#pragma unroll
        for (int jj = 0; jj < 2; jj++) {
            int j = 2 * t + jj;
            float p0 = __expf(S[j][0] - mn0);
            float p1 = __expf(S[j][1] - mn0);
            float p2 = __expf(S[j][2] - mn1);
            float p3 = __expf(S[j][3] - mn1);
            sum0 += p0 + p1; sum1 += p2 + p3;
            ah[2 * jj]     = pack2h(p0, p1);
            ah[2 * jj + 1] = pack2h(p2, p3);
        }
        int kchunk = NSTART + 2 * t + lhalf;
#pragma unroll
        for (int np = 0; np < 2; np++) {
            uint32_t r0, r1, r2, r3;
            ldsm_x4(r0, r1, r2, r3,
                    vth + (uint32_t)((np * 16 + lrow) * 432 + kchunk * 16));
            uint32_t b0[2] = {r0, r2}, b1[2] = {r1, r3};
            mma16816h(o[2 * np], ah, b0);
            mma16816h(o[2 * np + 1], ah, b1);
        }
    }
}

__global__ __launch_bounds__(256, 2) void fattn_kernel()
{
    extern __shared__ char smb[];
    const uint32_t sb = smem_u32(smb);
    const int b = blockIdx.x, h = blockIdx.y;
    const int tid = threadIdx.x;

    // ---- stage q*scale/k hi/lo + v single (fp16); Vt transposed ----
    const float* base = g_qkv + (size_t)b * NQ * KVN + h * HD;
    for (int idx = tid; idx < 208 * 32; idx += 256) {
        int n = idx >> 5, d = idx & 31;
        float qv = 0.f, kv = 0.f, vv = 0.f;
        if (n < NQ) {
            const float* row = base + (size_t)n * KVN;
            qv = row[d] * SCALE;
            kv = row[128 + d];
            vv = row[256 + d];
        }
        __half qhh = __float2half(qv);
        __half qll = __float2half(qv - __half2float(qhh));
        __half khh = __float2half(kv);
        __half kll = __float2half(kv - __half2float(khh));
        *(__half*)(smb + AQH + n * 80 + d * 2) = qhh;
        *(__half*)(smb + AQL + n * 80 + d * 2) = qll;
        *(__half*)(smb + AKH + n * 80 + d * 2) = khh;
        *(__half*)(smb + AKL + n * 80 + d * 2) = kll;
        *(__half*)(smb + AVTH + d * 432 + n * 2) = __float2half(vv);
    }
    __syncthreads();

    const int w = tid >> 5, lane = tid & 31;
    for (int s = w; s < 13; s += 8) {
        const int m0 = s * 16;
        const int row0 = m0 + (lane >> 2), row1 = row0 + 8;
        const int rc0 = min(row0, NQ - 1), rc1 = min(row1, NQ - 1);
        const float* bias0 = g_bias + ((size_t)h * NQ + rc0) * NCP + (lane & 3) * 2;
        const float* bias1 = g_bias + ((size_t)h * NQ + rc1) * NCP + (lane & 3) * 2;

        float o[4][4];
#pragma unroll
        for (int n = 0; n < 4; n++)
#pragma unroll
            for (int q = 0; q < 4; q++) o[n][q] = 0.f;
        float mo0 = -1e30f, mo1 = -1e30f, sum0 = 0.f, sum1 = 0.f;

        half_pass<0, 14>(sb + AQH, sb + AQL, sb + AKH, sb + AKL, sb + AVTH,
                         bias0, bias1, m0, lane, o, mo0, mo1, sum0, sum1);
        half_pass<14, 12>(sb + AQH, sb + AQL, sb + AKH, sb + AKL, sb + AVTH,
                          bias0, bias1, m0, lane, o, mo0, mo1, sum0, sum1);

        sum0 += __shfl_xor_sync(0xffffffffu, sum0, 1);
        sum0 += __shfl_xor_sync(0xffffffffu, sum0, 2);
        sum1 += __shfl_xor_sync(0xffffffffu, sum1, 1);
        sum1 += __shfl_xor_sync(0xffffffffu, sum1, 2);
        float i0 = 1.f / sum0, i1 = 1.f / sum1;

#pragma unroll
        for (int n = 0; n < 4; n++) {
            int d0 = n * 8 + (lane & 3) * 2;
            if (row0 < NQ)
                *(float2*)&g_att[((size_t)b * NQ + row0) * CDIM + h * HD + d0] =
                    make_float2(o[n][0] * i0, o[n][1] * i0);
            if (row1 < NQ)
                *(float2*)&g_att[((size_t)b * NQ + row1) * CDIM + h * HD + d0] =
                    make_float2(o[n][2] * i1, o[n][3] * i1);
        }
    }
}

// ============================================================
// launch
// ============================================================
extern "C" void kernel_launch(void* const* d_in, const int* in_sizes, int n_in,
                              void* d_out, int out_size)
{
    const float* x     = (const float*)d_in[0];
    const float* wq    = (const float*)d_in[1];
    const float* wkv   = (const float*)d_in[2];
    const float* wproj = (const float*)d_in[3];
    const float* bproj = (const float*)d_in[4];
    const float* pp_w  = (const float*)d_in[5];
    const float* pp_b  = (const float*)d_in[6];
    const float* ln1_g = (const float*)d_in[7];
    const float* ln1_b = (const float*)d_in[8];
    const float* l1_w  = (const float*)d_in[9];
    const float* l1_b  = (const float*)d_in[10];
    const float* ln2_g = (const float*)d_in[11];
    const float* ln2_b = (const float*)d_in[12];
    const float* l2_w  = (const float*)d_in[13];
    const float* l2_b  = (const float*)d_in[14];
    const float* ln3_g = (const float*)d_in[15];
    const float* ln3_b = (const float*)d_in[16];
    const float* l3_w  = (const float*)d_in[17];
    const float* l3_b  = (const float*)d_in[18];
    float* out = (float*)d_out;

    cudaFuncSetAttribute(hmma_gemm_kernel,
                         cudaFuncAttributeMaxDynamicSharedMemorySize, GSMEM);
    cudaFuncSetAttribute(fattn_kernel,
                         cudaFuncAttributeMaxDynamicSharedMemorySize, ATTN_SMEM);

    pos_mlp_kernel<<<3, 256>>>(pp_w, pp_b, ln1_g, ln1_b, l1_w, l1_b,
                               ln2_g, ln2_b, l2_w, l2_b,
                               ln3_g, ln3_b, l3_w, l3_b);

    bias_prep_kernel<<<(NH * NQ * NCP + 255) / 256, 256>>>();

    wprep_kernel<<<256, 256>>>(wq, wkv, wproj);

    // QKV: x @ [wq|wkv] -> g_qkv (fp32)
    hmma_gemm_kernel<<<MTOT / 128, 256, GSMEM>>>(0, x, nullptr, nullptr);

    // flash attention -> g_att (fp32)
    fattn_kernel<<<dim3(BATCH, NH), 256, ATTN_SMEM>>>();

    // Proj: g_att @ wproj + bproj -> out (fp32)
    hmma_gemm_kernel<<<MTOT / 128, 256, GSMEM>>>(1, nullptr, out, bproj);
}